// round 5
// baseline (speedup 1.0000x reference)
#include <cuda_runtime.h>
#include <cuda_bf16.h>
#include <math.h>
#include <stdint.h>

#define Bb 16
#define Cc 256
#define CC2 512
#define Ll 8192
#define EPSV 1e-5f
#define TLI 62
#define NTILES 133           // ceil(8192/62)

// scratch
__device__ float g_gate[Bb * Cc * Ll];
__device__ float g_pool[Bb * Cc];
__device__ float g_scale[Bb * Cc];
// weights, bf16 split, panel-major: [p = k/16][m][16]
__device__ __nv_bfloat16 g_w1h[131072], g_w1l[131072];
__device__ __nv_bfloat16 g_w2h[65536],  g_w2l[65536];

// ---------------- helpers ----------------
__device__ __forceinline__ uint32_t smem_u32(const void* p) {
    uint32_t a;
    asm("{ .reg .u64 t; cvta.to.shared.u64 t, %1; cvt.u32.u64 %0, t; }" : "=r"(a) : "l"(p));
    return a;
}
__device__ __forceinline__ void ldsm4(uint32_t* r, uint32_t addr) {
    asm volatile("ldmatrix.sync.aligned.m8n8.x4.shared.b16 {%0,%1,%2,%3}, [%4];"
        : "=r"(r[0]), "=r"(r[1]), "=r"(r[2]), "=r"(r[3]) : "r"(addr));
}
__device__ __forceinline__ void mma16816(float* c, const uint32_t* a, const uint32_t* b) {
    asm volatile("mma.sync.aligned.m16n8k16.row.col.f32.bf16.bf16.f32 "
        "{%0,%1,%2,%3}, {%4,%5,%6,%7}, {%8,%9}, {%0,%1,%2,%3};"
        : "+f"(c[0]), "+f"(c[1]), "+f"(c[2]), "+f"(c[3])
        : "r"(a[0]), "r"(a[1]), "r"(a[2]), "r"(a[3]), "r"(b[0]), "r"(b[1]));
}
__device__ __forceinline__ void bf16_split(float v, unsigned short* hi, unsigned short* lo) {
    __nv_bfloat16 h = __float2bfloat16(v);
    __nv_bfloat16 l = __float2bfloat16(v - __bfloat162float(h));
    *hi = *reinterpret_cast<unsigned short*>(&h);
    *lo = *reinterpret_cast<unsigned short*>(&l);
}
// B-tile byte offset: row l (n dim), channel c (k dim), swizzled for ldmatrix.
__device__ __forceinline__ uint32_t bswz(int l, int c) {
    return (uint32_t)(l * 512 + ((((c >> 3) ^ (l & 7)) << 4) | ((c & 7) * 2)));
}
// z staging word offset with XOR swizzle (conflict-free frag stores AND row reads)
__device__ __forceinline__ int zswz(int m, int l) {
    return m * 64 + (l ^ ((m & 7) << 3));
}

// ---------------------------------------------------------------------------
// K0: split weights to bf16 hi/lo, panel-major; zero g_pool
// ---------------------------------------------------------------------------
__global__ __launch_bounds__(256) void k0_split(const float* __restrict__ w1,
                                                const float* __restrict__ w2)
{
    int gi = blockIdx.x * 256 + threadIdx.x;
    if (gi < Bb * Cc) g_pool[gi] = 0.f;
    int idx = gi;
    if (idx < 131072) {
        int m = idx >> 8, k = idx & 255;
        unsigned short h, l;
        bf16_split(w1[idx], &h, &l);
        int off = ((k >> 4) * 512 + m) * 16 + (k & 15);
        *(unsigned short*)&g_w1h[off] = h;
        *(unsigned short*)&g_w1l[off] = l;
    } else {
        idx -= 131072;
        if (idx < 65536) {
            int m = idx >> 8, k = idx & 255;
            unsigned short h, l;
            bf16_split(w2[idx], &h, &l);
            int off = ((k >> 4) * 256 + m) * 16 + (k & 15);
            *(unsigned short*)&g_w2h[off] = h;
            *(unsigned short*)&g_w2l[off] = l;
        }
    }
}

// ---------------------------------------------------------------------------
// K1: LN + pw1 (mma.sync) + dwconv + SimpleGate + fused pool -> g_gate/g_pool
// smem: [0,64K) B hi|lo; [64K,96K) A 2bufs x (hi 8K|lo 8K);
//       [96K,160K) z1; [160K,224K) z2; [224K,+2.5K) red/stat
// ---------------------------------------------------------------------------
#define K1_B   0
#define K1_A   65536
#define K1_Z1  98304
#define K1_Z2  163840
#define K1_RED 229376
#define K1_SMEM 231936

__global__ __launch_bounds__(512) void k1_ln_pw1(
    const float* __restrict__ x, const float* __restrict__ gamma,
    const float* __restrict__ beta, const float* __restrict__ b1,
    const float* __restrict__ wd, const float* __restrict__ bd_)
{
    extern __shared__ char sm[];
    float* xf   = (float*)(sm + K1_Z1);
    float* red  = (float*)(sm + K1_RED);
    float* stat = (float*)(sm + K1_RED + 2048);
    const uint32_t smb = smem_u32(sm);
    const int b    = blockIdx.y;
    const int tile = blockIdx.x;
    const int l0   = tile * TLI - 1;
    const int tid  = threadIdx.x;
    const int w    = tid >> 5, lane = tid & 31;

    // ---- load x tile [256 c][64 l] ----
    for (int i = tid; i < Cc * 64; i += 512) {
        int c = i >> 6, l = i & 63;
        int lg = l0 + l;
        float v = 0.f;
        if (lg >= 0 && lg < Ll) v = x[(b * Cc + c) * Ll + lg];
        xf[i] = v;
    }
    __syncthreads();

    // ---- LN stats (first 256 threads) ----
    if (tid < 256) {
        int l = tid & 63, sub = tid >> 6;
        float s = 0.f, sq = 0.f;
        for (int c = sub; c < Cc; c += 4) {
            float v = xf[c * 64 + l];
            s += v; sq += v * v;
        }
        red[sub * 64 + l] = s;
        red[256 + sub * 64 + l] = sq;
    }
    __syncthreads();
    if (tid < 64) {
        float s  = red[tid] + red[64 + tid] + red[128 + tid] + red[192 + tid];
        float sq = red[256 + tid] + red[320 + tid] + red[384 + tid] + red[448 + tid];
        float mu = s * (1.f / Cc);
        float var = sq * (1.f / Cc) - mu * mu;
        stat[tid] = mu;
        stat[64 + tid] = rsqrtf(var + EPSV);
    }
    __syncthreads();

    // ---- normalize + bf16 split -> B tile ----
    for (int i = tid; i < 128 * 64; i += 512) {
        int cp = i >> 6, l = i & 63;
        int c = cp * 2;
        float mu = stat[l], rs = stat[64 + l];
        float v0 = (xf[c * 64 + l] - mu) * rs * __ldg(&gamma[c]) + __ldg(&beta[c]);
        float v1 = (xf[(c + 1) * 64 + l] - mu) * rs * __ldg(&gamma[c + 1]) + __ldg(&beta[c + 1]);
        unsigned short h0, h1, lo0, lo1;
        bf16_split(v0, &h0, &lo0);
        bf16_split(v1, &h1, &lo1);
        uint32_t by = bswz(l, c);
        *(uint32_t*)(sm + K1_B + by)         = (uint32_t)h0 | ((uint32_t)h1 << 16);
        *(uint32_t*)(sm + K1_B + 32768 + by) = (uint32_t)lo0 | ((uint32_t)lo1 << 16);
    }
    __syncthreads();

    // ---- fragment addressing: warp w owns rows w*16..w*16+15 ----
    const int lr  = lane & 7;
    const int gb0 = (lane >> 3) & 1;
    const int gb1 = lane >> 4;
    const uint32_t aBase = smb + K1_A + (uint32_t)((w * 16 + (lane & 15)) * 32 + gb1 * 16);
    uint32_t bBase[4];
    #pragma unroll
    for (int bp = 0; bp < 4; bp++)
        bBase[bp] = smb + K1_B + (uint32_t)((bp * 16 + gb1 * 8 + lr) * 512);

    // ---- GEMM: two M-passes of 256 rows, 16 warps x 1 m-tile ----
    for (int pass = 0; pass < 2; ++pass) {
        float acc[8][4];
        #pragma unroll
        for (int nt = 0; nt < 8; nt++)
            #pragma unroll
            for (int q = 0; q < 4; q++) acc[nt][q] = 0.f;

        const int4* srcH = (const int4*)g_w1h + (size_t)(pass * 512 + tid);
        const int4* srcL = (const int4*)g_w1l + (size_t)(pass * 512 + tid);

        {   // panel 0 -> buf 0
            int4 h0 = srcH[0], q0 = srcL[0];
            ((int4*)(sm + K1_A))[tid]       = h0;
            ((int4*)(sm + K1_A))[512 + tid] = q0;
        }

        for (int p = 0; p < 16; ++p) {
            int4 nh, nl;
            if (p < 15) {
                nh = srcH[(p + 1) * 1024];
                nl = srcL[(p + 1) * 1024];
            }
            __syncthreads();
            const uint32_t ab = aBase + (uint32_t)((p & 1) * 16384);
            uint32_t Ah[4], Al[4];
            ldsm4(Ah, ab);
            ldsm4(Al, ab + 8192);
            uint32_t kx = (uint32_t)(((p * 2 + gb0) ^ lr) << 4);
            uint32_t Bh[16], Bl[16];
            #pragma unroll
            for (int bp = 0; bp < 4; bp++) {
                ldsm4(&Bh[bp * 4], bBase[bp] + kx);
                ldsm4(&Bl[bp * 4], bBase[bp] + 32768 + kx);
            }
            #pragma unroll
            for (int nt = 0; nt < 8; nt++) {
                mma16816(acc[nt], Ah, &Bh[nt * 2]);
                mma16816(acc[nt], Ah, &Bl[nt * 2]);
                mma16816(acc[nt], Al, &Bh[nt * 2]);
            }
            if (p < 15) {
                int4* d = (int4*)(sm + K1_A + ((p + 1) & 1) * 16384);
                d[tid] = nh; d[512 + tid] = nl;
            }
        }

        // store z (+bias) to smem (XOR-swizzled)
        float* zb = (float*)(sm + (pass == 0 ? K1_Z1 : K1_Z2));
        int r = w * 16 + (lane >> 2);
        float bi0 = __ldg(&b1[pass * 256 + r]);
        float bi1 = __ldg(&b1[pass * 256 + r + 8]);
        #pragma unroll
        for (int nt = 0; nt < 8; nt++) {
            int c = nt * 8 + (lane & 3) * 2;
            int w0 = zswz(r, c), w1i = zswz(r + 8, c);
            zb[w0]     = acc[nt][0] + bi0;
            zb[w0 + 1] = acc[nt][1] + bi0;
            zb[w1i]     = acc[nt][2] + bi1;
            zb[w1i + 1] = acc[nt][3] + bi1;
        }
    }
    __syncthreads();

    // ---- depthwise conv + SimpleGate + fused pool accumulation ----
    float* z1 = (float*)(sm + K1_Z1);
    float* z2 = (float*)(sm + K1_Z2);
    float psum = 0.f;
    int curm = -1;
    for (int idx = tid; idx < Cc * TLI; idx += 512) {
        int m = idx / TLI;
        int l = 1 + (idx - m * TLI);
        int lg = l0 + l;
        if (m != curm) {
            if (curm >= 0 && psum != 0.f)
                atomicAdd(&g_pool[b * Cc + curm], psum * (1.f / Ll));
            curm = m; psum = 0.f;
        }
        if (lg >= Ll) continue;
        bool lok = (lg > 0), rok = (lg < Ll - 1);

        float a_l = lok ? z1[zswz(m, l - 1)] : 0.f;
        float a_c = z1[zswz(m, l)];
        float a_r = rok ? z1[zswz(m, l + 1)] : 0.f;
        float d1 = __ldg(&wd[m * 3 + 0]) * a_l + __ldg(&wd[m * 3 + 1]) * a_c +
                   __ldg(&wd[m * 3 + 2]) * a_r + __ldg(&bd_[m]);

        int m2 = m + Cc;
        float b_l = lok ? z2[zswz(m, l - 1)] : 0.f;
        float b_c = z2[zswz(m, l)];
        float b_r = rok ? z2[zswz(m, l + 1)] : 0.f;
        float d2 = __ldg(&wd[m2 * 3 + 0]) * b_l + __ldg(&wd[m2 * 3 + 1]) * b_c +
                   __ldg(&wd[m2 * 3 + 2]) * b_r + __ldg(&bd_[m2]);

        float g = d1 * d2;
        g_gate[(size_t)(b * Cc + m) * Ll + lg] = g;
        psum += g;
    }
    if (curm >= 0 && psum != 0.f)
        atomicAdd(&g_pool[b * Cc + curm], psum * (1.f / Ll));
}

// ---------------------------------------------------------------------------
// K3: SCA scale = sigmoid(ws @ pool + bs); one warp per output
// ---------------------------------------------------------------------------
__global__ __launch_bounds__(256) void k3_scale(
    const float* __restrict__ ws, const float* __restrict__ bs)
{
    __shared__ float sp[Cc];
    const int b = blockIdx.x;
    const int w = threadIdx.x >> 5, lane = threadIdx.x & 31;
    const int c = blockIdx.y * 8 + w;
    sp[threadIdx.x] = g_pool[b * Cc + threadIdx.x];
    __syncthreads();
    const float4* wr = (const float4*)(ws + c * Cc);
    const float4* pp = (const float4*)sp;
    float4 a0 = __ldg(&wr[lane * 2]), a1 = __ldg(&wr[lane * 2 + 1]);
    float4 p0 = pp[lane * 2], p1 = pp[lane * 2 + 1];
    float s = a0.x * p0.x + a0.y * p0.y + a0.z * p0.z + a0.w * p0.w
            + a1.x * p1.x + a1.y * p1.y + a1.z * p1.z + a1.w * p1.w;
    #pragma unroll
    for (int o = 16; o; o >>= 1) s += __shfl_xor_sync(0xFFFFFFFFu, s, o);
    if (lane == 0)
        g_scale[b * Cc + c] = 1.f / (1.f + expf(-(s + __ldg(&bs[c]))));
}

// ---------------------------------------------------------------------------
// K4: pw2 (mma.sync) + bias + residual. 512 threads, 16 warps x 1 m-tile.
// smem: [0,64K) B hi|lo; [64K,96K) A 2bufs; [96K,160K) z
// ---------------------------------------------------------------------------
#define K4_B 0
#define K4_A 65536
#define K4_Z 98304
#define K4_SMEM 163840

__global__ __launch_bounds__(512) void k4_pw2(
    const float* __restrict__ x, const float* __restrict__ b2,
    float* __restrict__ out)
{
    extern __shared__ char sm[];
    const uint32_t smb = smem_u32(sm);
    const int b = blockIdx.y, tile = blockIdx.x, tid = threadIdx.x;
    const int w = tid >> 5, lane = tid & 31;
    const int l0 = tile * 64;

    // ---- B tile: gate*scale -> bf16 split ----
    for (int i = tid; i < 128 * 64; i += 512) {
        int cp = i >> 6, l = i & 63;
        int c = cp * 2;
        float v0 = g_gate[(size_t)(b * Cc + c) * Ll + l0 + l] * __ldg(&g_scale[b * Cc + c]);
        float v1 = g_gate[(size_t)(b * Cc + c + 1) * Ll + l0 + l] * __ldg(&g_scale[b * Cc + c + 1]);
        unsigned short h0, h1, lo0, lo1;
        bf16_split(v0, &h0, &lo0);
        bf16_split(v1, &h1, &lo1);
        uint32_t by = bswz(l, c);
        *(uint32_t*)(sm + K4_B + by)         = (uint32_t)h0 | ((uint32_t)h1 << 16);
        *(uint32_t*)(sm + K4_B + 32768 + by) = (uint32_t)lo0 | ((uint32_t)lo1 << 16);
    }

    const int lr  = lane & 7;
    const int gb0 = (lane >> 3) & 1;
    const int gb1 = lane >> 4;
    const uint32_t aBase = smb + K4_A + (uint32_t)((w * 16 + (lane & 15)) * 32 + gb1 * 16);
    uint32_t bBase[4];
    #pragma unroll
    for (int bp = 0; bp < 4; bp++)
        bBase[bp] = smb + K4_B + (uint32_t)((bp * 16 + gb1 * 8 + lr) * 512);

    float acc[8][4];
    #pragma unroll
    for (int nt = 0; nt < 8; nt++)
        #pragma unroll
        for (int q = 0; q < 4; q++) acc[nt][q] = 0.f;

    const int4* srcH = (const int4*)g_w2h + (size_t)tid;
    const int4* srcL = (const int4*)g_w2l + (size_t)tid;
    {
        int4 h0 = srcH[0], q0 = srcL[0];
        ((int4*)(sm + K4_A))[tid]       = h0;
        ((int4*)(sm + K4_A))[512 + tid] = q0;
    }
    __syncthreads();   // also covers B-tile writes

    for (int p = 0; p < 16; ++p) {
        int4 nh, nl;
        if (p < 15) {
            nh = srcH[(p + 1) * 512];
            nl = srcL[(p + 1) * 512];
        }
        if (p > 0) __syncthreads();
        const uint32_t ab = aBase + (uint32_t)((p & 1) * 16384);
        uint32_t Ah[4], Al[4];
        ldsm4(Ah, ab);
        ldsm4(Al, ab + 8192);
        uint32_t kx = (uint32_t)(((p * 2 + gb0) ^ lr) << 4);
        uint32_t Bh[16], Bl[16];
        #pragma unroll
        for (int bp = 0; bp < 4; bp++) {
            ldsm4(&Bh[bp * 4], bBase[bp] + kx);
            ldsm4(&Bl[bp * 4], bBase[bp] + 32768 + kx);
        }
        #pragma unroll
        for (int nt = 0; nt < 8; nt++) {
            mma16816(acc[nt], Ah, &Bh[nt * 2]);
            mma16816(acc[nt], Ah, &Bl[nt * 2]);
            mma16816(acc[nt], Al, &Bh[nt * 2]);
        }
        if (p < 15) {
            int4* d = (int4*)(sm + K4_A + ((p + 1) & 1) * 16384);
            d[tid] = nh; d[512 + tid] = nl;
        }
    }

    // stage z (XOR-swizzled)
    float* zb = (float*)(sm + K4_Z);
    {
        int r = w * 16 + (lane >> 2);
        #pragma unroll
        for (int nt = 0; nt < 8; nt++) {
            int c = nt * 8 + (lane & 3) * 2;
            int w0 = zswz(r, c), w1i = zswz(r + 8, c);
            zb[w0]      = acc[nt][0];
            zb[w0 + 1]  = acc[nt][1];
            zb[w1i]     = acc[nt][2];
            zb[w1i + 1] = acc[nt][3];
        }
    }
    __syncthreads();

    // out = z + b2 + x   (coalesced float4, de-swizzled read)
    for (int i = tid; i < Cc * 16; i += 512) {
        int m = i >> 4, lq = i & 15;
        int slot = lq ^ ((m & 7) << 1);
        float4 zv = *(const float4*)(zb + m * 64 + slot * 4);
        float bias = __ldg(&b2[m]);
        const float* xr = x + (size_t)(b * Cc + m) * Ll + l0 + lq * 4;
        float4 xv = *(const float4*)xr;
        float4 ov;
        ov.x = zv.x + bias + xv.x;
        ov.y = zv.y + bias + xv.y;
        ov.z = zv.z + bias + xv.z;
        ov.w = zv.w + bias + xv.w;
        *(float4*)(out + (size_t)(b * Cc + m) * Ll + l0 + lq * 4) = ov;
    }
}

// ---------------------------------------------------------------------------
extern "C" void kernel_launch(void* const* d_in, const int* in_sizes, int n_in,
                              void* d_out, int out_size)
{
    const float* x     = (const float*)d_in[0];
    const float* gamma = (const float*)d_in[1];
    const float* beta  = (const float*)d_in[2];
    const float* w1    = (const float*)d_in[3];
    const float* b1    = (const float*)d_in[4];
    const float* wd    = (const float*)d_in[5];
    const float* bd    = (const float*)d_in[6];
    const float* wsm   = (const float*)d_in[7];
    const float* bs    = (const float*)d_in[8];
    const float* w2    = (const float*)d_in[9];
    const float* b2    = (const float*)d_in[10];
    float* out = (float*)d_out;

    cudaFuncSetAttribute(k1_ln_pw1, cudaFuncAttributeMaxDynamicSharedMemorySize, K1_SMEM);
    cudaFuncSetAttribute(k4_pw2,    cudaFuncAttributeMaxDynamicSharedMemorySize, K4_SMEM);

    k0_split<<<768, 256>>>(w1, w2);
    dim3 g1(NTILES, Bb);
    k1_ln_pw1<<<g1, 512, K1_SMEM>>>(x, gamma, beta, b1, wd, bd);
    dim3 g3(Bb, 32);
    k3_scale<<<g3, 256>>>(wsm, bs);
    dim3 g4(Ll / 64, Bb);
    k4_pw2<<<g4, 512, K4_SMEM>>>(x, b2, out);
}

// round 6
// speedup vs baseline: 7.5556x; 7.5556x over previous
#include <cuda_runtime.h>
#include <cuda_bf16.h>
#include <math.h>
#include <stdint.h>

#define Bb 16
#define Cc 256
#define CC2 512
#define Ll 8192
#define EPSV 1e-5f
#define TLI 62
#define NTILES 133           // ceil(8192/62)

// scratch
__device__ float g_gate[Bb * Cc * Ll];
__device__ float g_pool[Bb * Cc];
__device__ float g_scale[Bb * Cc];
// weights, bf16 split, panel-major: [p = k/16][m][16]
__device__ __nv_bfloat16 g_w1h[131072], g_w1l[131072];
__device__ __nv_bfloat16 g_w2h[65536],  g_w2l[65536];

// ---------------- helpers ----------------
__device__ __forceinline__ uint32_t smem_u32(const void* p) {
    uint32_t a;
    asm("{ .reg .u64 t; cvta.to.shared.u64 t, %1; cvt.u32.u64 %0, t; }" : "=r"(a) : "l"(p));
    return a;
}
__device__ __forceinline__ void ldsm4(uint32_t* r, uint32_t addr) {
    asm volatile("ldmatrix.sync.aligned.m8n8.x4.shared.b16 {%0,%1,%2,%3}, [%4];"
        : "=r"(r[0]), "=r"(r[1]), "=r"(r[2]), "=r"(r[3]) : "r"(addr));
}
__device__ __forceinline__ void mma16816(float* c, const uint32_t* a, const uint32_t* b) {
    asm volatile("mma.sync.aligned.m16n8k16.row.col.f32.bf16.bf16.f32 "
        "{%0,%1,%2,%3}, {%4,%5,%6,%7}, {%8,%9}, {%0,%1,%2,%3};"
        : "+f"(c[0]), "+f"(c[1]), "+f"(c[2]), "+f"(c[3])
        : "r"(a[0]), "r"(a[1]), "r"(a[2]), "r"(a[3]), "r"(b[0]), "r"(b[1]));
}
__device__ __forceinline__ void bf16_split(float v, unsigned short* hi, unsigned short* lo) {
    __nv_bfloat16 h = __float2bfloat16(v);
    __nv_bfloat16 l = __float2bfloat16(v - __bfloat162float(h));
    *hi = *reinterpret_cast<unsigned short*>(&h);
    *lo = *reinterpret_cast<unsigned short*>(&l);
}
// B-tile byte offset: row l (n dim), channel c (k dim), swizzled for ldmatrix.
__device__ __forceinline__ uint32_t bswz(int l, int c) {
    return (uint32_t)(l * 512 + ((((c >> 3) ^ (l & 7)) << 4) | ((c & 7) * 2)));
}
// z staging word offset with XOR swizzle (conflict-free frag stores AND row reads)
__device__ __forceinline__ int zswz(int m, int l) {
    return m * 64 + (l ^ ((m & 7) << 3));
}

// ---------------------------------------------------------------------------
// K0: split weights to bf16 hi/lo, panel-major; zero g_pool
// ---------------------------------------------------------------------------
__global__ __launch_bounds__(256) void k0_split(const float* __restrict__ w1,
                                                const float* __restrict__ w2)
{
    int gi = blockIdx.x * 256 + threadIdx.x;
    if (gi < Bb * Cc) g_pool[gi] = 0.f;
    int idx = gi;
    if (idx < 131072) {
        int m = idx >> 8, k = idx & 255;
        unsigned short h, l;
        bf16_split(w1[idx], &h, &l);
        int off = ((k >> 4) * 512 + m) * 16 + (k & 15);
        *(unsigned short*)&g_w1h[off] = h;
        *(unsigned short*)&g_w1l[off] = l;
    } else {
        idx -= 131072;
        if (idx < 65536) {
            int m = idx >> 8, k = idx & 255;
            unsigned short h, l;
            bf16_split(w2[idx], &h, &l);
            int off = ((k >> 4) * 256 + m) * 16 + (k & 15);
            *(unsigned short*)&g_w2h[off] = h;
            *(unsigned short*)&g_w2l[off] = l;
        }
    }
}

// ---------------------------------------------------------------------------
// K1: LN + pw1 (mma.sync) + dwconv + SimpleGate + fused pool -> g_gate/g_pool
// smem: [0,64K) B hi|lo; [64K,96K) A 2bufs x (hi 8K|lo 8K);
//       [96K,160K) z1; [160K,224K) z2; [224K,+2.5K) red/stat
// ---------------------------------------------------------------------------
#define K1_B   0
#define K1_A   65536
#define K1_Z1  98304
#define K1_Z2  163840
#define K1_RED 229376
#define K1_SMEM 231936

__global__ __launch_bounds__(512) void k1_ln_pw1(
    const float* __restrict__ x, const float* __restrict__ gamma,
    const float* __restrict__ beta, const float* __restrict__ b1,
    const float* __restrict__ wd, const float* __restrict__ bd_)
{
    extern __shared__ char sm[];
    float* xf   = (float*)(sm + K1_Z1);
    float* red  = (float*)(sm + K1_RED);
    float* stat = (float*)(sm + K1_RED + 2048);
    const uint32_t smb = smem_u32(sm);
    const int b    = blockIdx.y;
    const int tile = blockIdx.x;
    const int l0   = tile * TLI - 1;
    const int tid  = threadIdx.x;
    const int w    = tid >> 5, lane = tid & 31;

    // ---- load x tile [256 c][64 l] ----
    for (int i = tid; i < Cc * 64; i += 512) {
        int c = i >> 6, l = i & 63;
        int lg = l0 + l;
        float v = 0.f;
        if (lg >= 0 && lg < Ll) v = x[(b * Cc + c) * Ll + lg];
        xf[i] = v;
    }
    __syncthreads();

    // ---- LN stats (first 256 threads) ----
    if (tid < 256) {
        int l = tid & 63, sub = tid >> 6;
        float s = 0.f, sq = 0.f;
        for (int c = sub; c < Cc; c += 4) {
            float v = xf[c * 64 + l];
            s += v; sq += v * v;
        }
        red[sub * 64 + l] = s;
        red[256 + sub * 64 + l] = sq;
    }
    __syncthreads();
    if (tid < 64) {
        float s  = red[tid] + red[64 + tid] + red[128 + tid] + red[192 + tid];
        float sq = red[256 + tid] + red[320 + tid] + red[384 + tid] + red[448 + tid];
        float mu = s * (1.f / Cc);
        float var = sq * (1.f / Cc) - mu * mu;
        stat[tid] = mu;
        stat[64 + tid] = rsqrtf(var + EPSV);
    }
    __syncthreads();

    // ---- normalize + bf16 split -> B tile ----
    for (int i = tid; i < 128 * 64; i += 512) {
        int cp = i >> 6, l = i & 63;
        int c = cp * 2;
        float mu = stat[l], rs = stat[64 + l];
        float v0 = (xf[c * 64 + l] - mu) * rs * __ldg(&gamma[c]) + __ldg(&beta[c]);
        float v1 = (xf[(c + 1) * 64 + l] - mu) * rs * __ldg(&gamma[c + 1]) + __ldg(&beta[c + 1]);
        unsigned short h0, h1, lo0, lo1;
        bf16_split(v0, &h0, &lo0);
        bf16_split(v1, &h1, &lo1);
        uint32_t by = bswz(l, c);
        *(uint32_t*)(sm + K1_B + by)         = (uint32_t)h0 | ((uint32_t)h1 << 16);
        *(uint32_t*)(sm + K1_B + 32768 + by) = (uint32_t)lo0 | ((uint32_t)lo1 << 16);
    }
    __syncthreads();

    // ---- fragment addressing: warp w owns rows w*16..w*16+15 ----
    const int lr  = lane & 7;
    const int gb0 = (lane >> 3) & 1;
    const int gb1 = lane >> 4;
    const uint32_t aBase = smb + K1_A + (uint32_t)((w * 16 + (lane & 15)) * 32 + gb1 * 16);
    uint32_t bBase[4];
    #pragma unroll
    for (int bp = 0; bp < 4; bp++)
        bBase[bp] = smb + K1_B + (uint32_t)((bp * 16 + gb1 * 8 + lr) * 512);

    // ---- GEMM: two M-passes of 256 rows, 16 warps x 1 m-tile ----
    for (int pass = 0; pass < 2; ++pass) {
        float acc[8][4];
        #pragma unroll
        for (int nt = 0; nt < 8; nt++)
            #pragma unroll
            for (int q = 0; q < 4; q++) acc[nt][q] = 0.f;

        const int4* srcH = (const int4*)g_w1h + (size_t)(pass * 512 + tid);
        const int4* srcL = (const int4*)g_w1l + (size_t)(pass * 512 + tid);

        {   // panel 0 -> buf 0
            int4 h0 = srcH[0], q0 = srcL[0];
            ((int4*)(sm + K1_A))[tid]       = h0;
            ((int4*)(sm + K1_A))[512 + tid] = q0;
        }

        for (int p = 0; p < 16; ++p) {
            int4 nh, nl;
            if (p < 15) {
                nh = srcH[(p + 1) * 1024];
                nl = srcL[(p + 1) * 1024];
            }
            __syncthreads();
            const uint32_t ab = aBase + (uint32_t)((p & 1) * 16384);
            uint32_t Ah[4], Al[4];
            ldsm4(Ah, ab);
            ldsm4(Al, ab + 8192);
            uint32_t kx = (uint32_t)(((p * 2 + gb0) ^ lr) << 4);
            uint32_t Bh[16], Bl[16];
            #pragma unroll
            for (int bp = 0; bp < 4; bp++) {
                ldsm4(&Bh[bp * 4], bBase[bp] + kx);
                ldsm4(&Bl[bp * 4], bBase[bp] + 32768 + kx);
            }
            #pragma unroll
            for (int nt = 0; nt < 8; nt++) {
                mma16816(acc[nt], Ah, &Bh[nt * 2]);
                mma16816(acc[nt], Ah, &Bl[nt * 2]);
                mma16816(acc[nt], Al, &Bh[nt * 2]);
            }
            if (p < 15) {
                int4* d = (int4*)(sm + K1_A + ((p + 1) & 1) * 16384);
                d[tid] = nh; d[512 + tid] = nl;
            }
        }

        // store z (+bias) to smem (XOR-swizzled)
        float* zb = (float*)(sm + (pass == 0 ? K1_Z1 : K1_Z2));
        int r = w * 16 + (lane >> 2);
        float bi0 = __ldg(&b1[pass * 256 + r]);
        float bi1 = __ldg(&b1[pass * 256 + r + 8]);
        #pragma unroll
        for (int nt = 0; nt < 8; nt++) {
            int c = nt * 8 + (lane & 3) * 2;
            int w0 = zswz(r, c), w1i = zswz(r + 8, c);
            zb[w0]     = acc[nt][0] + bi0;
            zb[w0 + 1] = acc[nt][1] + bi0;
            zb[w1i]     = acc[nt][2] + bi1;
            zb[w1i + 1] = acc[nt][3] + bi1;
        }
    }
    __syncthreads();

    // ---- dwconv + SimpleGate + pool: warp w owns m = w, w+16, ... (exclusive)
    float* z1 = (float*)(sm + K1_Z1);
    float* z2 = (float*)(sm + K1_Z2);
    for (int mi = 0; mi < 16; mi++) {
        const int m  = mi * 16 + w;
        const int m2 = m + Cc;
        const float wa0 = __ldg(&wd[m * 3 + 0]),  wa1 = __ldg(&wd[m * 3 + 1]),
                    wa2 = __ldg(&wd[m * 3 + 2]),  ba  = __ldg(&bd_[m]);
        const float wb0 = __ldg(&wd[m2 * 3 + 0]), wb1 = __ldg(&wd[m2 * 3 + 1]),
                    wb2 = __ldg(&wd[m2 * 3 + 2]), bb  = __ldg(&bd_[m2]);
        float* orow = g_gate + (size_t)(b * Cc + m) * Ll;
        float psum = 0.f;
        #pragma unroll
        for (int h = 0; h < 2; h++) {
            int l = 1 + h * 31 + lane;          // l in 1..62, lane<31 active
            int lg = l0 + l;
            if (lane < 31 && lg < Ll) {
                bool lok = (lg > 0), rok = (lg < Ll - 1);
                float a_l = lok ? z1[zswz(m, l - 1)] : 0.f;
                float a_c = z1[zswz(m, l)];
                float a_r = rok ? z1[zswz(m, l + 1)] : 0.f;
                float d1 = wa0 * a_l + wa1 * a_c + wa2 * a_r + ba;
                float b_l = lok ? z2[zswz(m, l - 1)] : 0.f;
                float b_c = z2[zswz(m, l)];
                float b_r = rok ? z2[zswz(m, l + 1)] : 0.f;
                float d2 = wb0 * b_l + wb1 * b_c + wb2 * b_r + bb;
                float g = d1 * d2;
                orow[lg] = g;
                psum += g;
            }
        }
        #pragma unroll
        for (int o = 16; o; o >>= 1) psum += __shfl_xor_sync(0xFFFFFFFFu, psum, o);
        if (lane == 0) red[m] = psum;           // exclusive writer per m
    }
    __syncthreads();
    if (tid < 256) {
        float v = red[tid];
        if (v != 0.f) atomicAdd(&g_pool[b * Cc + tid], v * (1.f / Ll));
    }
}

// ---------------------------------------------------------------------------
// K3: SCA scale = sigmoid(ws @ pool + bs); one warp per output
// ---------------------------------------------------------------------------
__global__ __launch_bounds__(256) void k3_scale(
    const float* __restrict__ ws, const float* __restrict__ bs)
{
    __shared__ float sp[Cc];
    const int b = blockIdx.x;
    const int w = threadIdx.x >> 5, lane = threadIdx.x & 31;
    const int c = blockIdx.y * 8 + w;
    sp[threadIdx.x] = g_pool[b * Cc + threadIdx.x];
    __syncthreads();
    const float4* wr = (const float4*)(ws + c * Cc);
    const float4* pp = (const float4*)sp;
    float4 a0 = __ldg(&wr[lane * 2]), a1 = __ldg(&wr[lane * 2 + 1]);
    float4 p0 = pp[lane * 2], p1 = pp[lane * 2 + 1];
    float s = a0.x * p0.x + a0.y * p0.y + a0.z * p0.z + a0.w * p0.w
            + a1.x * p1.x + a1.y * p1.y + a1.z * p1.z + a1.w * p1.w;
    #pragma unroll
    for (int o = 16; o; o >>= 1) s += __shfl_xor_sync(0xFFFFFFFFu, s, o);
    if (lane == 0)
        g_scale[b * Cc + c] = 1.f / (1.f + expf(-(s + __ldg(&bs[c]))));
}

// ---------------------------------------------------------------------------
// K4: pw2 (mma.sync) + bias + residual. 512 threads, 16 warps x 1 m-tile.
// smem: [0,64K) B hi|lo; [64K,96K) A 2bufs; [96K,160K) z
// ---------------------------------------------------------------------------
#define K4_B 0
#define K4_A 65536
#define K4_Z 98304
#define K4_SMEM 163840

__global__ __launch_bounds__(512) void k4_pw2(
    const float* __restrict__ x, const float* __restrict__ b2,
    float* __restrict__ out)
{
    extern __shared__ char sm[];
    const uint32_t smb = smem_u32(sm);
    const int b = blockIdx.y, tile = blockIdx.x, tid = threadIdx.x;
    const int w = tid >> 5, lane = tid & 31;
    const int l0 = tile * 64;

    // ---- B tile: gate*scale -> bf16 split ----
    for (int i = tid; i < 128 * 64; i += 512) {
        int cp = i >> 6, l = i & 63;
        int c = cp * 2;
        float v0 = g_gate[(size_t)(b * Cc + c) * Ll + l0 + l] * __ldg(&g_scale[b * Cc + c]);
        float v1 = g_gate[(size_t)(b * Cc + c + 1) * Ll + l0 + l] * __ldg(&g_scale[b * Cc + c + 1]);
        unsigned short h0, h1, lo0, lo1;
        bf16_split(v0, &h0, &lo0);
        bf16_split(v1, &h1, &lo1);
        uint32_t by = bswz(l, c);
        *(uint32_t*)(sm + K4_B + by)         = (uint32_t)h0 | ((uint32_t)h1 << 16);
        *(uint32_t*)(sm + K4_B + 32768 + by) = (uint32_t)lo0 | ((uint32_t)lo1 << 16);
    }

    const int lr  = lane & 7;
    const int gb0 = (lane >> 3) & 1;
    const int gb1 = lane >> 4;
    const uint32_t aBase = smb + K4_A + (uint32_t)((w * 16 + (lane & 15)) * 32 + gb1 * 16);
    uint32_t bBase[4];
    #pragma unroll
    for (int bp = 0; bp < 4; bp++)
        bBase[bp] = smb + K4_B + (uint32_t)((bp * 16 + gb1 * 8 + lr) * 512);

    float acc[8][4];
    #pragma unroll
    for (int nt = 0; nt < 8; nt++)
        #pragma unroll
        for (int q = 0; q < 4; q++) acc[nt][q] = 0.f;

    const int4* srcH = (const int4*)g_w2h + (size_t)tid;
    const int4* srcL = (const int4*)g_w2l + (size_t)tid;
    {
        int4 h0 = srcH[0], q0 = srcL[0];
        ((int4*)(sm + K4_A))[tid]       = h0;
        ((int4*)(sm + K4_A))[512 + tid] = q0;
    }
    __syncthreads();   // also covers B-tile writes

    for (int p = 0; p < 16; ++p) {
        int4 nh, nl;
        if (p < 15) {
            nh = srcH[(p + 1) * 512];
            nl = srcL[(p + 1) * 512];
        }
        if (p > 0) __syncthreads();
        const uint32_t ab = aBase + (uint32_t)((p & 1) * 16384);
        uint32_t Ah[4], Al[4];
        ldsm4(Ah, ab);
        ldsm4(Al, ab + 8192);
        uint32_t kx = (uint32_t)(((p * 2 + gb0) ^ lr) << 4);
        uint32_t Bh[16], Bl[16];
        #pragma unroll
        for (int bp = 0; bp < 4; bp++) {
            ldsm4(&Bh[bp * 4], bBase[bp] + kx);
            ldsm4(&Bl[bp * 4], bBase[bp] + 32768 + kx);
        }
        #pragma unroll
        for (int nt = 0; nt < 8; nt++) {
            mma16816(acc[nt], Ah, &Bh[nt * 2]);
            mma16816(acc[nt], Ah, &Bl[nt * 2]);
            mma16816(acc[nt], Al, &Bh[nt * 2]);
        }
        if (p < 15) {
            int4* d = (int4*)(sm + K4_A + ((p + 1) & 1) * 16384);
            d[tid] = nh; d[512 + tid] = nl;
        }
    }

    // stage z (XOR-swizzled)
    float* zb = (float*)(sm + K4_Z);
    {
        int r = w * 16 + (lane >> 2);
        #pragma unroll
        for (int nt = 0; nt < 8; nt++) {
            int c = nt * 8 + (lane & 3) * 2;
            int w0 = zswz(r, c), w1i = zswz(r + 8, c);
            zb[w0]      = acc[nt][0];
            zb[w0 + 1]  = acc[nt][1];
            zb[w1i]     = acc[nt][2];
            zb[w1i + 1] = acc[nt][3];
        }
    }
    __syncthreads();

    // out = z + b2 + x   (coalesced float4, de-swizzled read)
    for (int i = tid; i < Cc * 16; i += 512) {
        int m = i >> 4, lq = i & 15;
        int slot = lq ^ ((m & 7) << 1);
        float4 zv = *(const float4*)(zb + m * 64 + slot * 4);
        float bias = __ldg(&b2[m]);
        const float* xr = x + (size_t)(b * Cc + m) * Ll + l0 + lq * 4;
        float4 xv = *(const float4*)xr;
        float4 ov;
        ov.x = zv.x + bias + xv.x;
        ov.y = zv.y + bias + xv.y;
        ov.z = zv.z + bias + xv.z;
        ov.w = zv.w + bias + xv.w;
        *(float4*)(out + (size_t)(b * Cc + m) * Ll + l0 + lq * 4) = ov;
    }
}

// ---------------------------------------------------------------------------
extern "C" void kernel_launch(void* const* d_in, const int* in_sizes, int n_in,
                              void* d_out, int out_size)
{
    const float* x     = (const float*)d_in[0];
    const float* gamma = (const float*)d_in[1];
    const float* beta  = (const float*)d_in[2];
    const float* w1    = (const float*)d_in[3];
    const float* b1    = (const float*)d_in[4];
    const float* wd    = (const float*)d_in[5];
    const float* bd    = (const float*)d_in[6];
    const float* wsm   = (const float*)d_in[7];
    const float* bs    = (const float*)d_in[8];
    const float* w2    = (const float*)d_in[9];
    const float* b2    = (const float*)d_in[10];
    float* out = (float*)d_out;

    cudaFuncSetAttribute(k1_ln_pw1, cudaFuncAttributeMaxDynamicSharedMemorySize, K1_SMEM);
    cudaFuncSetAttribute(k4_pw2,    cudaFuncAttributeMaxDynamicSharedMemorySize, K4_SMEM);

    k0_split<<<768, 256>>>(w1, w2);
    dim3 g1(NTILES, Bb);
    k1_ln_pw1<<<g1, 512, K1_SMEM>>>(x, gamma, beta, b1, wd, bd);
    dim3 g3(Bb, 32);
    k3_scale<<<g3, 256>>>(wsm, bs);
    dim3 g4(Ll / 64, Bb);
    k4_pw2<<<g4, 512, K4_SMEM>>>(x, b2, out);
}

// round 7
// speedup vs baseline: 8.9567x; 1.1854x over previous
#include <cuda_runtime.h>
#include <cuda_bf16.h>
#include <math.h>
#include <stdint.h>

#define Bb 16
#define Cc 256
#define CC2 512
#define Ll 8192
#define EPSV 1e-5f
#define TLI 62
#define NTILES 133           // ceil(8192/62)

// scratch
__device__ float g_gate[Bb * Cc * Ll];
__device__ float g_pool[Bb * Cc];
__device__ float g_scale[Bb * Cc];
// weights, bf16 split, panel-major: [p = k/16][m][16]
__device__ __nv_bfloat16 g_w1h[131072], g_w1l[131072];
__device__ __nv_bfloat16 g_w2h[65536],  g_w2l[65536];

// ---------------- helpers ----------------
__device__ __forceinline__ uint32_t smem_u32(const void* p) {
    uint32_t a;
    asm("{ .reg .u64 t; cvta.to.shared.u64 t, %1; cvt.u32.u64 %0, t; }" : "=r"(a) : "l"(p));
    return a;
}
__device__ __forceinline__ void ldsm4(uint32_t* r, uint32_t addr) {
    asm volatile("ldmatrix.sync.aligned.m8n8.x4.shared.b16 {%0,%1,%2,%3}, [%4];"
        : "=r"(r[0]), "=r"(r[1]), "=r"(r[2]), "=r"(r[3]) : "r"(addr));
}
__device__ __forceinline__ void mma16816(float* c, const uint32_t* a, const uint32_t* b) {
    asm volatile("mma.sync.aligned.m16n8k16.row.col.f32.bf16.bf16.f32 "
        "{%0,%1,%2,%3}, {%4,%5,%6,%7}, {%8,%9}, {%0,%1,%2,%3};"
        : "+f"(c[0]), "+f"(c[1]), "+f"(c[2]), "+f"(c[3])
        : "r"(a[0]), "r"(a[1]), "r"(a[2]), "r"(a[3]), "r"(b[0]), "r"(b[1]));
}
__device__ __forceinline__ void bf16_split(float v, unsigned short* hi, unsigned short* lo) {
    __nv_bfloat16 h = __float2bfloat16(v);
    __nv_bfloat16 l = __float2bfloat16(v - __bfloat162float(h));
    *hi = *reinterpret_cast<unsigned short*>(&h);
    *lo = *reinterpret_cast<unsigned short*>(&l);
}
// B-tile byte offset: row l (n dim), channel c (k dim), swizzled for ldmatrix.
__device__ __forceinline__ uint32_t bswz(int l, int c) {
    return (uint32_t)(l * 512 + ((((c >> 3) ^ (l & 7)) << 4) | ((c & 7) * 2)));
}
// z staging word offset with XOR swizzle
__device__ __forceinline__ int zswz(int m, int l) {
    return m * 64 + (l ^ ((m & 7) << 3));
}

// ---------------------------------------------------------------------------
// K0: split weights to bf16 hi/lo, panel-major; zero g_pool
// ---------------------------------------------------------------------------
__global__ __launch_bounds__(256) void k0_split(const float* __restrict__ w1,
                                                const float* __restrict__ w2)
{
    int gi = blockIdx.x * 256 + threadIdx.x;
    if (gi < Bb * Cc) g_pool[gi] = 0.f;
    int idx = gi;
    if (idx < 131072) {
        int m = idx >> 8, k = idx & 255;
        unsigned short h, l;
        bf16_split(w1[idx], &h, &l);
        int off = ((k >> 4) * 512 + m) * 16 + (k & 15);
        *(unsigned short*)&g_w1h[off] = h;
        *(unsigned short*)&g_w1l[off] = l;
    } else {
        idx -= 131072;
        if (idx < 65536) {
            int m = idx >> 8, k = idx & 255;
            unsigned short h, l;
            bf16_split(w2[idx], &h, &l);
            int off = ((k >> 4) * 256 + m) * 16 + (k & 15);
            *(unsigned short*)&g_w2h[off] = h;
            *(unsigned short*)&g_w2l[off] = l;
        }
    }
}

// ---------------------------------------------------------------------------
// K1: LN + pw1 (single M=512 GEMM) + dwconv + SimpleGate + fused pool
// smem: [0,64K) B hi|lo (later z1); [64K,128K) A 2bufs x 32K (xf staging
//       first, later z2); [128K,+2.5K) red/stat
// ---------------------------------------------------------------------------
#define K1_B   0
#define K1_A   65536
#define K1_RED 131072
#define K1_SMEM 133632

__global__ __launch_bounds__(512) void k1_ln_pw1(
    const float* __restrict__ x, const float* __restrict__ gamma,
    const float* __restrict__ beta, const float* __restrict__ b1,
    const float* __restrict__ wd, const float* __restrict__ bd_)
{
    extern __shared__ char sm[];
    float* xf   = (float*)(sm + K1_A);           // [256][64] staging
    float* red  = (float*)(sm + K1_RED);
    float* stat = (float*)(sm + K1_RED + 2048);
    const uint32_t smb = smem_u32(sm);
    const int b    = blockIdx.y;
    const int tile = blockIdx.x;
    const int l0   = tile * TLI - 1;
    const int tid  = threadIdx.x;
    const int w    = tid >> 5, lane = tid & 31;

    // ---- load x tile [256 c][64 l] ----
    for (int i = tid; i < Cc * 64; i += 512) {
        int c = i >> 6, l = i & 63;
        int lg = l0 + l;
        float v = 0.f;
        if (lg >= 0 && lg < Ll) v = x[(b * Cc + c) * Ll + lg];
        xf[i] = v;
    }
    __syncthreads();

    // ---- LN stats ----
    if (tid < 256) {
        int l = tid & 63, sub = tid >> 6;
        float s = 0.f, sq = 0.f;
        for (int c = sub; c < Cc; c += 4) {
            float v = xf[c * 64 + l];
            s += v; sq += v * v;
        }
        red[sub * 64 + l] = s;
        red[256 + sub * 64 + l] = sq;
    }
    __syncthreads();
    if (tid < 64) {
        float s  = red[tid] + red[64 + tid] + red[128 + tid] + red[192 + tid];
        float sq = red[256 + tid] + red[320 + tid] + red[384 + tid] + red[448 + tid];
        float mu = s * (1.f / Cc);
        float var = sq * (1.f / Cc) - mu * mu;
        stat[tid] = mu;
        stat[64 + tid] = rsqrtf(var + EPSV);
    }
    __syncthreads();

    // ---- normalize + bf16 split -> B tile at [0,64K) ----
    for (int i = tid; i < 128 * 64; i += 512) {
        int cp = i >> 6, l = i & 63;
        int c = cp * 2;
        float mu = stat[l], rs = stat[64 + l];
        float v0 = (xf[c * 64 + l] - mu) * rs * __ldg(&gamma[c]) + __ldg(&beta[c]);
        float v1 = (xf[(c + 1) * 64 + l] - mu) * rs * __ldg(&gamma[c + 1]) + __ldg(&beta[c + 1]);
        unsigned short h0, h1, lo0, lo1;
        bf16_split(v0, &h0, &lo0);
        bf16_split(v1, &h1, &lo1);
        uint32_t by = bswz(l, c);
        *(uint32_t*)(sm + K1_B + by)         = (uint32_t)h0 | ((uint32_t)h1 << 16);
        *(uint32_t*)(sm + K1_B + 32768 + by) = (uint32_t)lo0 | ((uint32_t)lo1 << 16);
    }
    __syncthreads();   // B ready; xf (A region) now reusable

    // ---- fragment addressing: warp w owns m-tiles (w*16) and (256 + w*16)
    const int lr  = lane & 7;
    const int gb0 = (lane >> 3) & 1;
    const int gb1 = lane >> 4;
    const uint32_t aBase = smb + K1_A + (uint32_t)((w * 16 + (lane & 15)) * 32 + gb1 * 16);
    uint32_t bBase[4];
    #pragma unroll
    for (int bp = 0; bp < 4; bp++)
        bBase[bp] = smb + K1_B + (uint32_t)((bp * 16 + gb1 * 8 + lr) * 512);

    // ---- single GEMM: M=512, K=256, N=64; double-buffered A panels ----
    float acc[2][8][4];
    #pragma unroll
    for (int mt = 0; mt < 2; mt++)
        #pragma unroll
        for (int nt = 0; nt < 8; nt++)
            #pragma unroll
            for (int q = 0; q < 4; q++) acc[mt][nt][q] = 0.f;

    const int4* srcH = (const int4*)g_w1h;   // panel p at p*1024 int4
    const int4* srcL = (const int4*)g_w1l;
    {   // panel 0 -> buf 0: hi [0,16K) lo [16K,32K)
        int4* d = (int4*)(sm + K1_A);
        d[tid]        = srcH[tid];
        d[512 + tid]  = srcH[512 + tid];
        d[1024 + tid] = srcL[tid];
        d[1536 + tid] = srcL[512 + tid];
    }

    for (int p = 0; p < 16; ++p) {
        int4 nh0, nh1, nl0, nl1;
        if (p < 15) {
            int base = (p + 1) * 1024;
            nh0 = srcH[base + tid];       nh1 = srcH[base + 512 + tid];
            nl0 = srcL[base + tid];       nl1 = srcL[base + 512 + tid];
        }
        __syncthreads();
        const uint32_t ab = aBase + (uint32_t)((p & 1) * 32768);
        uint32_t A0h[4], A0l[4], A1h[4], A1l[4];
        ldsm4(A0h, ab);                    // m-tile 0, hi
        ldsm4(A0l, ab + 16384);            // m-tile 0, lo
        ldsm4(A1h, ab + 8192);             // m-tile 1 (rows +256), hi
        ldsm4(A1l, ab + 8192 + 16384);     // m-tile 1, lo
        uint32_t kx = (uint32_t)(((p * 2 + gb0) ^ lr) << 4);
        #pragma unroll
        for (int bp = 0; bp < 4; bp++) {
            uint32_t Bh[4], Bl[4];
            ldsm4(Bh, bBase[bp] + kx);
            ldsm4(Bl, bBase[bp] + 32768 + kx);
            #pragma unroll
            for (int q = 0; q < 2; q++) {
                int nt = bp * 2 + q;
                mma16816(acc[0][nt], A0h, &Bh[q * 2]);
                mma16816(acc[0][nt], A0h, &Bl[q * 2]);
                mma16816(acc[0][nt], A0l, &Bh[q * 2]);
                mma16816(acc[1][nt], A1h, &Bh[q * 2]);
                mma16816(acc[1][nt], A1h, &Bl[q * 2]);
                mma16816(acc[1][nt], A1l, &Bh[q * 2]);
            }
        }
        if (p < 15) {
            int4* d = (int4*)(sm + K1_A + ((p + 1) & 1) * 32768);
            d[tid] = nh0; d[512 + tid] = nh1;
            d[1024 + tid] = nl0; d[1536 + tid] = nl1;
        }
    }
    __syncthreads();   // all reads of A/B done before aliasing as z1/z2

    // ---- store z (+bias) to smem: z1 aliases B, z2 aliases A ----
    #pragma unroll
    for (int mt = 0; mt < 2; mt++) {
        float* zb = (float*)(sm + (mt == 0 ? K1_B : K1_A));
        int r = w * 16 + (lane >> 2);
        float bi0 = __ldg(&b1[mt * 256 + r]);
        float bi1 = __ldg(&b1[mt * 256 + r + 8]);
        #pragma unroll
        for (int nt = 0; nt < 8; nt++) {
            int c = nt * 8 + (lane & 3) * 2;
            int w0 = zswz(r, c), w1i = zswz(r + 8, c);
            zb[w0]      = acc[mt][nt][0] + bi0;
            zb[w0 + 1]  = acc[mt][nt][1] + bi0;
            zb[w1i]     = acc[mt][nt][2] + bi1;
            zb[w1i + 1] = acc[mt][nt][3] + bi1;
        }
    }
    __syncthreads();

    // ---- dwconv + SimpleGate + pool: warp w owns m = w, w+16, ... ----
    float* z1 = (float*)(sm + K1_B);
    float* z2 = (float*)(sm + K1_A);
    for (int mi = 0; mi < 16; mi++) {
        const int m  = mi * 16 + w;
        const int m2 = m + Cc;
        const float wa0 = __ldg(&wd[m * 3 + 0]),  wa1 = __ldg(&wd[m * 3 + 1]),
                    wa2 = __ldg(&wd[m * 3 + 2]),  ba  = __ldg(&bd_[m]);
        const float wb0 = __ldg(&wd[m2 * 3 + 0]), wb1 = __ldg(&wd[m2 * 3 + 1]),
                    wb2 = __ldg(&wd[m2 * 3 + 2]), bb  = __ldg(&bd_[m2]);
        float* orow = g_gate + (size_t)(b * Cc + m) * Ll;
        float psum = 0.f;
        #pragma unroll
        for (int h = 0; h < 2; h++) {
            int l = 1 + h * 31 + lane;          // l in 1..62, lane<31 active
            int lg = l0 + l;
            if (lane < 31 && lg < Ll) {
                bool lok = (lg > 0), rok = (lg < Ll - 1);
                float a_l = lok ? z1[zswz(m, l - 1)] : 0.f;
                float a_c = z1[zswz(m, l)];
                float a_r = rok ? z1[zswz(m, l + 1)] : 0.f;
                float d1 = wa0 * a_l + wa1 * a_c + wa2 * a_r + ba;
                float b_l = lok ? z2[zswz(m, l - 1)] : 0.f;
                float b_c = z2[zswz(m, l)];
                float b_r = rok ? z2[zswz(m, l + 1)] : 0.f;
                float d2 = wb0 * b_l + wb1 * b_c + wb2 * b_r + bb;
                float g = d1 * d2;
                orow[lg] = g;
                psum += g;
            }
        }
        #pragma unroll
        for (int o = 16; o; o >>= 1) psum += __shfl_xor_sync(0xFFFFFFFFu, psum, o);
        if (lane == 0) red[m] = psum;
    }
    __syncthreads();
    if (tid < 256) {
        float v = red[tid];
        if (v != 0.f) atomicAdd(&g_pool[b * Cc + tid], v * (1.f / Ll));
    }
}

// ---------------------------------------------------------------------------
// K3: SCA scale = sigmoid(ws @ pool + bs); one warp per output
// ---------------------------------------------------------------------------
__global__ __launch_bounds__(256) void k3_scale(
    const float* __restrict__ ws, const float* __restrict__ bs)
{
    __shared__ float sp[Cc];
    const int b = blockIdx.x;
    const int w = threadIdx.x >> 5, lane = threadIdx.x & 31;
    const int c = blockIdx.y * 8 + w;
    sp[threadIdx.x] = g_pool[b * Cc + threadIdx.x];
    __syncthreads();
    const float4* wr = (const float4*)(ws + c * Cc);
    const float4* pp = (const float4*)sp;
    float4 a0 = __ldg(&wr[lane * 2]), a1 = __ldg(&wr[lane * 2 + 1]);
    float4 p0 = pp[lane * 2], p1 = pp[lane * 2 + 1];
    float s = a0.x * p0.x + a0.y * p0.y + a0.z * p0.z + a0.w * p0.w
            + a1.x * p1.x + a1.y * p1.y + a1.z * p1.z + a1.w * p1.w;
    #pragma unroll
    for (int o = 16; o; o >>= 1) s += __shfl_xor_sync(0xFFFFFFFFu, s, o);
    if (lane == 0)
        g_scale[b * Cc + c] = 1.f / (1.f + expf(-(s + __ldg(&bs[c]))));
}

// ---------------------------------------------------------------------------
// K4: pw2 + bias + residual. 256 threads, 8 warps x 2 m-tiles, 2 CTAs/SM.
// smem: [0,64K) B hi|lo (later z); [64K,96K) A 2bufs x 16K
// ---------------------------------------------------------------------------
#define K4_B 0
#define K4_A 65536
#define K4_SMEM 98304

__global__ __launch_bounds__(256, 2) void k4_pw2(
    const float* __restrict__ x, const float* __restrict__ b2,
    float* __restrict__ out)
{
    extern __shared__ char sm[];
    const uint32_t smb = smem_u32(sm);
    const int b = blockIdx.y, tile = blockIdx.x, tid = threadIdx.x;
    const int w = tid >> 5, lane = tid & 31;
    const int l0 = tile * 64;

    // ---- B tile: gate*scale -> bf16 split ----
    for (int i = tid; i < 128 * 64; i += 256) {
        int cp = i >> 6, l = i & 63;
        int c = cp * 2;
        float v0 = g_gate[(size_t)(b * Cc + c) * Ll + l0 + l] * __ldg(&g_scale[b * Cc + c]);
        float v1 = g_gate[(size_t)(b * Cc + c + 1) * Ll + l0 + l] * __ldg(&g_scale[b * Cc + c + 1]);
        unsigned short h0, h1, lo0, lo1;
        bf16_split(v0, &h0, &lo0);
        bf16_split(v1, &h1, &lo1);
        uint32_t by = bswz(l, c);
        *(uint32_t*)(sm + K4_B + by)         = (uint32_t)h0 | ((uint32_t)h1 << 16);
        *(uint32_t*)(sm + K4_B + 32768 + by) = (uint32_t)lo0 | ((uint32_t)lo1 << 16);
    }

    const int lr  = lane & 7;
    const int gb0 = (lane >> 3) & 1;
    const int gb1 = lane >> 4;
    const uint32_t aBase = smb + K4_A + (uint32_t)((w * 16 + (lane & 15)) * 32 + gb1 * 16);
    uint32_t bBase[4];
    #pragma unroll
    for (int bp = 0; bp < 4; bp++)
        bBase[bp] = smb + K4_B + (uint32_t)((bp * 16 + gb1 * 8 + lr) * 512);

    float acc[2][8][4];
    #pragma unroll
    for (int mt = 0; mt < 2; mt++)
        #pragma unroll
        for (int nt = 0; nt < 8; nt++)
            #pragma unroll
            for (int q = 0; q < 4; q++) acc[mt][nt][q] = 0.f;

    const int4* srcH = (const int4*)g_w2h;   // panel p at p*512 int4
    const int4* srcL = (const int4*)g_w2l;
    {   // panel 0 -> buf 0: hi [0,8K) lo [8K,16K)
        int4* d = (int4*)(sm + K4_A);
        d[tid]       = srcH[tid];
        d[256 + tid] = srcH[256 + tid];
        d[512 + tid] = srcL[tid];
        d[768 + tid] = srcL[256 + tid];
    }
    __syncthreads();   // also covers B-tile writes

    for (int p = 0; p < 16; ++p) {
        int4 nh0, nh1, nl0, nl1;
        if (p < 15) {
            int base = (p + 1) * 512;
            nh0 = srcH[base + tid];       nh1 = srcH[base + 256 + tid];
            nl0 = srcL[base + tid];       nl1 = srcL[base + 256 + tid];
        }
        if (p > 0) __syncthreads();
        const uint32_t ab = aBase + (uint32_t)((p & 1) * 16384);
        uint32_t A0h[4], A0l[4], A1h[4], A1l[4];
        ldsm4(A0h, ab);
        ldsm4(A0l, ab + 8192);
        ldsm4(A1h, ab + 4096);             // rows +128
        ldsm4(A1l, ab + 4096 + 8192);
        uint32_t kx = (uint32_t)(((p * 2 + gb0) ^ lr) << 4);
        #pragma unroll
        for (int bp = 0; bp < 4; bp++) {
            uint32_t Bh[4], Bl[4];
            ldsm4(Bh, bBase[bp] + kx);
            ldsm4(Bl, bBase[bp] + 32768 + kx);
            #pragma unroll
            for (int q = 0; q < 2; q++) {
                int nt = bp * 2 + q;
                mma16816(acc[0][nt], A0h, &Bh[q * 2]);
                mma16816(acc[0][nt], A0h, &Bl[q * 2]);
                mma16816(acc[0][nt], A0l, &Bh[q * 2]);
                mma16816(acc[1][nt], A1h, &Bh[q * 2]);
                mma16816(acc[1][nt], A1h, &Bl[q * 2]);
                mma16816(acc[1][nt], A1l, &Bh[q * 2]);
            }
        }
        if (p < 15) {
            int4* d = (int4*)(sm + K4_A + ((p + 1) & 1) * 16384);
            d[tid] = nh0; d[256 + tid] = nh1;
            d[512 + tid] = nl0; d[768 + tid] = nl1;
        }
    }
    __syncthreads();   // B reads done before aliasing as z

    // stage z (XOR-swizzled), aliases B region
    float* zb = (float*)(sm + K4_B);
    #pragma unroll
    for (int mt = 0; mt < 2; mt++) {
        int r = mt * 128 + w * 16 + (lane >> 2);
        #pragma unroll
        for (int nt = 0; nt < 8; nt++) {
            int c = nt * 8 + (lane & 3) * 2;
            int w0 = zswz(r, c), w1i = zswz(r + 8, c);
            zb[w0]      = acc[mt][nt][0];
            zb[w0 + 1]  = acc[mt][nt][1];
            zb[w1i]     = acc[mt][nt][2];
            zb[w1i + 1] = acc[mt][nt][3];
        }
    }
    __syncthreads();

    // out = z + b2 + x   (coalesced float4, de-swizzled read)
    for (int i = tid; i < Cc * 16; i += 256) {
        int m = i >> 4, lq = i & 15;
        int slot = lq ^ ((m & 7) << 1);
        float4 zv = *(const float4*)(zb + m * 64 + slot * 4);
        float bias = __ldg(&b2[m]);
        const float* xr = x + (size_t)(b * Cc + m) * Ll + l0 + lq * 4;
        float4 xv = *(const float4*)xr;
        float4 ov;
        ov.x = zv.x + bias + xv.x;
        ov.y = zv.y + bias + xv.y;
        ov.z = zv.z + bias + xv.z;
        ov.w = zv.w + bias + xv.w;
        *(float4*)(out + (size_t)(b * Cc + m) * Ll + l0 + lq * 4) = ov;
    }
}

// ---------------------------------------------------------------------------
extern "C" void kernel_launch(void* const* d_in, const int* in_sizes, int n_in,
                              void* d_out, int out_size)
{
    const float* x     = (const float*)d_in[0];
    const float* gamma = (const float*)d_in[1];
    const float* beta  = (const float*)d_in[2];
    const float* w1    = (const float*)d_in[3];
    const float* b1    = (const float*)d_in[4];
    const float* wd    = (const float*)d_in[5];
    const float* bd    = (const float*)d_in[6];
    const float* wsm   = (const float*)d_in[7];
    const float* bs    = (const float*)d_in[8];
    const float* w2    = (const float*)d_in[9];
    const float* b2    = (const float*)d_in[10];
    float* out = (float*)d_out;

    cudaFuncSetAttribute(k1_ln_pw1, cudaFuncAttributeMaxDynamicSharedMemorySize, K1_SMEM);
    cudaFuncSetAttribute(k4_pw2,    cudaFuncAttributeMaxDynamicSharedMemorySize, K4_SMEM);

    k0_split<<<768, 256>>>(w1, w2);
    dim3 g1(NTILES, Bb);
    k1_ln_pw1<<<g1, 512, K1_SMEM>>>(x, gamma, beta, b1, wd, bd);
    dim3 g3(Bb, 32);
    k3_scale<<<g3, 256>>>(wsm, bs);
    dim3 g4(Ll / 64, Bb);
    k4_pw2<<<g4, 256, K4_SMEM>>>(x, b2, out);
}

// round 8
// speedup vs baseline: 10.4932x; 1.1715x over previous
#include <cuda_runtime.h>
#include <cuda_bf16.h>
#include <math.h>
#include <stdint.h>

#define Bb 16
#define Cc 256
#define CC2 512
#define Ll 8192
#define EPSV 1e-5f
#define TLI 62
#define NTILES 133           // ceil(8192/62)

// scratch
__device__ float g_gate[Bb * Cc * Ll];
__device__ float g_pool[Bb * Cc];
__device__ float g_scale[Bb * Cc];
// weights pre-packed as mma.m16n8k16 A-fragments:
//   index = (p * MT + mt) * 32 + lane, uint4 = {a0,a1,a2,a3}
__device__ uint4 g_w1f[16384], g_w1fl[16384];   // MT=32 (M=512), 16 panels
__device__ uint4 g_w2f[8192],  g_w2fl[8192];    // MT=16 (M=256), 16 panels

// ---------------- helpers ----------------
__device__ __forceinline__ uint32_t smem_u32(const void* p) {
    uint32_t a;
    asm("{ .reg .u64 t; cvta.to.shared.u64 t, %1; cvt.u32.u64 %0, t; }" : "=r"(a) : "l"(p));
    return a;
}
__device__ __forceinline__ void ldsm4(uint32_t* r, uint32_t addr) {
    asm volatile("ldmatrix.sync.aligned.m8n8.x4.shared.b16 {%0,%1,%2,%3}, [%4];"
        : "=r"(r[0]), "=r"(r[1]), "=r"(r[2]), "=r"(r[3]) : "r"(addr));
}
__device__ __forceinline__ void mma16816(float* c, const uint32_t* a, const uint32_t* b) {
    asm volatile("mma.sync.aligned.m16n8k16.row.col.f32.bf16.bf16.f32 "
        "{%0,%1,%2,%3}, {%4,%5,%6,%7}, {%8,%9}, {%0,%1,%2,%3};"
        : "+f"(c[0]), "+f"(c[1]), "+f"(c[2]), "+f"(c[3])
        : "r"(a[0]), "r"(a[1]), "r"(a[2]), "r"(a[3]), "r"(b[0]), "r"(b[1]));
}
__device__ __forceinline__ void bf16_split(float v, unsigned short* hi, unsigned short* lo) {
    __nv_bfloat16 h = __float2bfloat16(v);
    __nv_bfloat16 l = __float2bfloat16(v - __bfloat162float(h));
    *hi = *reinterpret_cast<unsigned short*>(&h);
    *lo = *reinterpret_cast<unsigned short*>(&l);
}
__device__ __forceinline__ uint32_t pack_hi2(float v0, float v1, uint32_t* lo) {
    unsigned short h0, h1, l0, l1;
    bf16_split(v0, &h0, &l0);
    bf16_split(v1, &h1, &l1);
    *lo = (uint32_t)l0 | ((uint32_t)l1 << 16);
    return (uint32_t)h0 | ((uint32_t)h1 << 16);
}
// B-tile byte offset: row l (n dim), channel c (k dim), swizzled for ldmatrix.
__device__ __forceinline__ uint32_t bswz(int l, int c) {
    return (uint32_t)(l * 512 + ((((c >> 3) ^ (l & 7)) << 4) | ((c & 7) * 2)));
}
// z staging word offset with XOR swizzle
__device__ __forceinline__ int zswz(int m, int l) {
    return m * 64 + (l ^ ((m & 7) << 3));
}

// ---------------------------------------------------------------------------
// K0: pack weights into mma A-fragment layout (hi/lo split); zero g_pool
// ---------------------------------------------------------------------------
__global__ __launch_bounds__(256) void k0_split(const float* __restrict__ w1,
                                                const float* __restrict__ w2)
{
    int idx = blockIdx.x * 256 + threadIdx.x;
    if (idx < Bb * Cc) g_pool[idx] = 0.f;

    if (idx < 16384) {                 // w1 fragments: MT=32
        int p = idx >> 10, rem = idx & 1023;
        int mt = rem >> 5, lane = rem & 31;
        int r = mt * 16 + (lane >> 2);
        int c = p * 16 + (lane & 3) * 2;
        const float* A = w1;
        uint4 hi, lo;
        hi.x = pack_hi2(A[r * Cc + c],           A[r * Cc + c + 1],           &lo.x);
        hi.y = pack_hi2(A[(r + 8) * Cc + c],     A[(r + 8) * Cc + c + 1],     &lo.y);
        hi.z = pack_hi2(A[r * Cc + c + 8],       A[r * Cc + c + 9],           &lo.z);
        hi.w = pack_hi2(A[(r + 8) * Cc + c + 8], A[(r + 8) * Cc + c + 9],     &lo.w);
        g_w1f[idx] = hi;  g_w1fl[idx] = lo;
    } else if (idx < 24576) {          // w2 fragments: MT=16
        int i2 = idx - 16384;
        int p = i2 >> 9, rem = i2 & 511;
        int mt = rem >> 5, lane = rem & 31;
        int r = mt * 16 + (lane >> 2);
        int c = p * 16 + (lane & 3) * 2;
        const float* A = w2;
        uint4 hi, lo;
        hi.x = pack_hi2(A[r * Cc + c],           A[r * Cc + c + 1],           &lo.x);
        hi.y = pack_hi2(A[(r + 8) * Cc + c],     A[(r + 8) * Cc + c + 1],     &lo.y);
        hi.z = pack_hi2(A[r * Cc + c + 8],       A[r * Cc + c + 9],           &lo.z);
        hi.w = pack_hi2(A[(r + 8) * Cc + c + 8], A[(r + 8) * Cc + c + 9],     &lo.w);
        g_w2f[i2] = hi;   g_w2fl[i2] = lo;
    }
}

// ---------------------------------------------------------------------------
// K1: LN + pw1 (M=512, barrier-free mainloop) + dwconv + gate + fused pool
// smem: [0,64K) B hi|lo (later z1); [64K,128K) xf [256][64] (later z2);
//       [128K,+2.5K) red/stat
// ---------------------------------------------------------------------------
#define K1_B   0
#define K1_XF  65536
#define K1_RED 131072
#define K1_SMEM 133632

__global__ __launch_bounds__(512, 1) void k1_ln_pw1(
    const float* __restrict__ x, const float* __restrict__ gamma,
    const float* __restrict__ beta, const float* __restrict__ b1,
    const float* __restrict__ wd, const float* __restrict__ bd_)
{
    extern __shared__ char sm[];
    float* xf   = (float*)(sm + K1_XF);
    float* red  = (float*)(sm + K1_RED);
    float* stat = (float*)(sm + K1_RED + 2048);
    const uint32_t smb = smem_u32(sm);
    const int b    = blockIdx.y;
    const int tile = blockIdx.x;
    const int l0   = tile * TLI - 1;
    const int tid  = threadIdx.x;
    const int w    = tid >> 5, lane = tid & 31;

    // ---- load x tile [256 c][64 l] ----
    for (int i = tid; i < Cc * 64; i += 512) {
        int c = i >> 6, l = i & 63;
        int lg = l0 + l;
        float v = 0.f;
        if (lg >= 0 && lg < Ll) v = x[(b * Cc + c) * Ll + lg];
        xf[i] = v;
    }
    __syncthreads();

    // ---- LN stats ----
    if (tid < 256) {
        int l = tid & 63, sub = tid >> 6;
        float s = 0.f, sq = 0.f;
        for (int c = sub; c < Cc; c += 4) {
            float v = xf[c * 64 + l];
            s += v; sq += v * v;
        }
        red[sub * 64 + l] = s;
        red[256 + sub * 64 + l] = sq;
    }
    __syncthreads();
    if (tid < 64) {
        float s  = red[tid] + red[64 + tid] + red[128 + tid] + red[192 + tid];
        float sq = red[256 + tid] + red[320 + tid] + red[384 + tid] + red[448 + tid];
        float mu = s * (1.f / Cc);
        float var = sq * (1.f / Cc) - mu * mu;
        stat[tid] = mu;
        stat[64 + tid] = rsqrtf(var + EPSV);
    }
    __syncthreads();

    // ---- normalize + bf16 split -> B tile ----
    for (int i = tid; i < 128 * 64; i += 512) {
        int cp = i >> 6, l = i & 63;
        int c = cp * 2;
        float mu = stat[l], rs = stat[64 + l];
        float v0 = (xf[c * 64 + l] - mu) * rs * __ldg(&gamma[c]) + __ldg(&beta[c]);
        float v1 = (xf[(c + 1) * 64 + l] - mu) * rs * __ldg(&gamma[c + 1]) + __ldg(&beta[c + 1]);
        uint32_t lop;
        uint32_t hip = pack_hi2(v0, v1, &lop);
        uint32_t by = bswz(l, c);
        *(uint32_t*)(sm + K1_B + by)         = hip;
        *(uint32_t*)(sm + K1_B + 32768 + by) = lop;
    }
    __syncthreads();   // B resident for the whole mainloop

    const int lr  = lane & 7;
    const int gb0 = (lane >> 3) & 1;
    const int gb1 = lane >> 4;
    uint32_t bBase[4];
    #pragma unroll
    for (int bp = 0; bp < 4; bp++)
        bBase[bp] = smb + K1_B + (uint32_t)((bp * 16 + gb1 * 8 + lr) * 512);

    // ---- barrier-free GEMM: M=512, A fragments via LDG ----
    float acc[2][8][4];
    #pragma unroll
    for (int mt = 0; mt < 2; mt++)
        #pragma unroll
        for (int nt = 0; nt < 8; nt++)
            #pragma unroll
            for (int q = 0; q < 4; q++) acc[mt][nt][q] = 0.f;

    const uint4* A0H = g_w1f  + w * 32 + lane;          // mt = w
    const uint4* A0L = g_w1fl + w * 32 + lane;
    const uint4* A1H = g_w1f  + (16 + w) * 32 + lane;   // mt = 16 + w
    const uint4* A1L = g_w1fl + (16 + w) * 32 + lane;

    #pragma unroll 4
    for (int p = 0; p < 16; ++p) {
        uint4 a0h = __ldg(A0H + p * 1024);
        uint4 a0l = __ldg(A0L + p * 1024);
        uint4 a1h = __ldg(A1H + p * 1024);
        uint4 a1l = __ldg(A1L + p * 1024);
        uint32_t kx = (uint32_t)(((p * 2 + gb0) ^ lr) << 4);
        #pragma unroll
        for (int bp = 0; bp < 4; bp++) {
            uint32_t Bh[4], Bl[4];
            ldsm4(Bh, bBase[bp] + kx);
            ldsm4(Bl, bBase[bp] + 32768 + kx);
            #pragma unroll
            for (int q = 0; q < 2; q++) {
                int nt = bp * 2 + q;
                mma16816(acc[0][nt], (const uint32_t*)&a0h, &Bh[q * 2]);
                mma16816(acc[0][nt], (const uint32_t*)&a0h, &Bl[q * 2]);
                mma16816(acc[0][nt], (const uint32_t*)&a0l, &Bh[q * 2]);
                mma16816(acc[1][nt], (const uint32_t*)&a1h, &Bh[q * 2]);
                mma16816(acc[1][nt], (const uint32_t*)&a1h, &Bl[q * 2]);
                mma16816(acc[1][nt], (const uint32_t*)&a1l, &Bh[q * 2]);
            }
        }
    }
    __syncthreads();   // all B reads done before aliasing as z1

    // ---- store z (+bias): z1 aliases B, z2 aliases xf ----
    #pragma unroll
    for (int mt = 0; mt < 2; mt++) {
        float* zb = (float*)(sm + (mt == 0 ? K1_B : K1_XF));
        int r = w * 16 + (lane >> 2);
        float bi0 = __ldg(&b1[mt * 256 + r]);
        float bi1 = __ldg(&b1[mt * 256 + r + 8]);
        #pragma unroll
        for (int nt = 0; nt < 8; nt++) {
            int c = nt * 8 + (lane & 3) * 2;
            int w0 = zswz(r, c), w1i = zswz(r + 8, c);
            zb[w0]      = acc[mt][nt][0] + bi0;
            zb[w0 + 1]  = acc[mt][nt][1] + bi0;
            zb[w1i]     = acc[mt][nt][2] + bi1;
            zb[w1i + 1] = acc[mt][nt][3] + bi1;
        }
    }
    __syncthreads();

    // ---- dwconv + SimpleGate + pool: warp w owns m = w, w+16, ... ----
    float* z1 = (float*)(sm + K1_B);
    float* z2 = (float*)(sm + K1_XF);
    for (int mi = 0; mi < 16; mi++) {
        const int m  = mi * 16 + w;
        const int m2 = m + Cc;
        const float wa0 = __ldg(&wd[m * 3 + 0]),  wa1 = __ldg(&wd[m * 3 + 1]),
                    wa2 = __ldg(&wd[m * 3 + 2]),  ba  = __ldg(&bd_[m]);
        const float wb0 = __ldg(&wd[m2 * 3 + 0]), wb1 = __ldg(&wd[m2 * 3 + 1]),
                    wb2 = __ldg(&wd[m2 * 3 + 2]), bb  = __ldg(&bd_[m2]);
        float* orow = g_gate + (size_t)(b * Cc + m) * Ll;
        float psum = 0.f;
        #pragma unroll
        for (int h = 0; h < 2; h++) {
            int l = 1 + h * 31 + lane;          // l in 1..62, lane<31 active
            int lg = l0 + l;
            if (lane < 31 && lg < Ll) {
                bool lok = (lg > 0), rok = (lg < Ll - 1);
                float a_l = lok ? z1[zswz(m, l - 1)] : 0.f;
                float a_c = z1[zswz(m, l)];
                float a_r = rok ? z1[zswz(m, l + 1)] : 0.f;
                float d1 = wa0 * a_l + wa1 * a_c + wa2 * a_r + ba;
                float b_l = lok ? z2[zswz(m, l - 1)] : 0.f;
                float b_c = z2[zswz(m, l)];
                float b_r = rok ? z2[zswz(m, l + 1)] : 0.f;
                float d2 = wb0 * b_l + wb1 * b_c + wb2 * b_r + bb;
                float g = d1 * d2;
                orow[lg] = g;
                psum += g;
            }
        }
        #pragma unroll
        for (int o = 16; o; o >>= 1) psum += __shfl_xor_sync(0xFFFFFFFFu, psum, o);
        if (lane == 0) red[m] = psum;
    }
    __syncthreads();
    if (tid < 256) {
        float v = red[tid];
        if (v != 0.f) atomicAdd(&g_pool[b * Cc + tid], v * (1.f / Ll));
    }
}

// ---------------------------------------------------------------------------
// K3: SCA scale = sigmoid(ws @ pool + bs); one warp per output
// ---------------------------------------------------------------------------
__global__ __launch_bounds__(256) void k3_scale(
    const float* __restrict__ ws, const float* __restrict__ bs)
{
    __shared__ float sp[Cc];
    const int b = blockIdx.x;
    const int w = threadIdx.x >> 5, lane = threadIdx.x & 31;
    const int c = blockIdx.y * 8 + w;
    sp[threadIdx.x] = g_pool[b * Cc + threadIdx.x];
    __syncthreads();
    const float4* wr = (const float4*)(ws + c * Cc);
    const float4* pp = (const float4*)sp;
    float4 a0 = __ldg(&wr[lane * 2]), a1 = __ldg(&wr[lane * 2 + 1]);
    float4 p0 = pp[lane * 2], p1 = pp[lane * 2 + 1];
    float s = a0.x * p0.x + a0.y * p0.y + a0.z * p0.z + a0.w * p0.w
            + a1.x * p1.x + a1.y * p1.y + a1.z * p1.z + a1.w * p1.w;
    #pragma unroll
    for (int o = 16; o; o >>= 1) s += __shfl_xor_sync(0xFFFFFFFFu, s, o);
    if (lane == 0)
        g_scale[b * Cc + c] = 1.f / (1.f + expf(-(s + __ldg(&bs[c]))));
}

// ---------------------------------------------------------------------------
// K4: pw2 (barrier-free mainloop) + bias + residual. 256 thr, 2 CTAs/SM.
// smem: [0,64K) B hi|lo (later z)
// ---------------------------------------------------------------------------
#define K4_B 0
#define K4_SMEM 65536

__global__ __launch_bounds__(256, 2) void k4_pw2(
    const float* __restrict__ x, const float* __restrict__ b2,
    float* __restrict__ out)
{
    extern __shared__ char sm[];
    const uint32_t smb = smem_u32(sm);
    const int b = blockIdx.y, tile = blockIdx.x, tid = threadIdx.x;
    const int w = tid >> 5, lane = tid & 31;
    const int l0 = tile * 64;

    // ---- B tile: gate*scale -> bf16 split ----
    for (int i = tid; i < 128 * 64; i += 256) {
        int cp = i >> 6, l = i & 63;
        int c = cp * 2;
        float v0 = g_gate[(size_t)(b * Cc + c) * Ll + l0 + l] * __ldg(&g_scale[b * Cc + c]);
        float v1 = g_gate[(size_t)(b * Cc + c + 1) * Ll + l0 + l] * __ldg(&g_scale[b * Cc + c + 1]);
        uint32_t lop;
        uint32_t hip = pack_hi2(v0, v1, &lop);
        uint32_t by = bswz(l, c);
        *(uint32_t*)(sm + K4_B + by)         = hip;
        *(uint32_t*)(sm + K4_B + 32768 + by) = lop;
    }
    __syncthreads();

    const int lr  = lane & 7;
    const int gb0 = (lane >> 3) & 1;
    const int gb1 = lane >> 4;
    uint32_t bBase[4];
    #pragma unroll
    for (int bp = 0; bp < 4; bp++)
        bBase[bp] = smb + K4_B + (uint32_t)((bp * 16 + gb1 * 8 + lr) * 512);

    float acc[2][8][4];
    #pragma unroll
    for (int mt = 0; mt < 2; mt++)
        #pragma unroll
        for (int nt = 0; nt < 8; nt++)
            #pragma unroll
            for (int q = 0; q < 4; q++) acc[mt][nt][q] = 0.f;

    const uint4* A0H = g_w2f  + w * 32 + lane;          // mt = w
    const uint4* A0L = g_w2fl + w * 32 + lane;
    const uint4* A1H = g_w2f  + (8 + w) * 32 + lane;    // mt = 8 + w
    const uint4* A1L = g_w2fl + (8 + w) * 32 + lane;

    #pragma unroll 4
    for (int p = 0; p < 16; ++p) {
        uint4 a0h = __ldg(A0H + p * 512);
        uint4 a0l = __ldg(A0L + p * 512);
        uint4 a1h = __ldg(A1H + p * 512);
        uint4 a1l = __ldg(A1L + p * 512);
        uint32_t kx = (uint32_t)(((p * 2 + gb0) ^ lr) << 4);
        #pragma unroll
        for (int bp = 0; bp < 4; bp++) {
            uint32_t Bh[4], Bl[4];
            ldsm4(Bh, bBase[bp] + kx);
            ldsm4(Bl, bBase[bp] + 32768 + kx);
            #pragma unroll
            for (int q = 0; q < 2; q++) {
                int nt = bp * 2 + q;
                mma16816(acc[0][nt], (const uint32_t*)&a0h, &Bh[q * 2]);
                mma16816(acc[0][nt], (const uint32_t*)&a0h, &Bl[q * 2]);
                mma16816(acc[0][nt], (const uint32_t*)&a0l, &Bh[q * 2]);
                mma16816(acc[1][nt], (const uint32_t*)&a1h, &Bh[q * 2]);
                mma16816(acc[1][nt], (const uint32_t*)&a1h, &Bl[q * 2]);
                mma16816(acc[1][nt], (const uint32_t*)&a1l, &Bh[q * 2]);
            }
        }
    }
    __syncthreads();   // B reads done before aliasing as z

    // stage z (XOR-swizzled), aliases B region
    float* zb = (float*)(sm + K4_B);
    #pragma unroll
    for (int mt = 0; mt < 2; mt++) {
        int r = mt * 128 + w * 16 + (lane >> 2);
        #pragma unroll
        for (int nt = 0; nt < 8; nt++) {
            int c = nt * 8 + (lane & 3) * 2;
            int w0 = zswz(r, c), w1i = zswz(r + 8, c);
            zb[w0]      = acc[mt][nt][0];
            zb[w0 + 1]  = acc[mt][nt][1];
            zb[w1i]     = acc[mt][nt][2];
            zb[w1i + 1] = acc[mt][nt][3];
        }
    }
    __syncthreads();

    // out = z + b2 + x   (coalesced float4, de-swizzled read)
    for (int i = tid; i < Cc * 16; i += 256) {
        int m = i >> 4, lq = i & 15;
        int slot = lq ^ ((m & 7) << 1);
        float4 zv = *(const float4*)(zb + m * 64 + slot * 4);
        float bias = __ldg(&b2[m]);
        const float* xr = x + (size_t)(b * Cc + m) * Ll + l0 + lq * 4;
        float4 xv = *(const float4*)xr;
        float4 ov;
        ov.x = zv.x + bias + xv.x;
        ov.y = zv.y + bias + xv.y;
        ov.z = zv.z + bias + xv.z;
        ov.w = zv.w + bias + xv.w;
        *(float4*)(out + (size_t)(b * Cc + m) * Ll + l0 + lq * 4) = ov;
    }
}

// ---------------------------------------------------------------------------
extern "C" void kernel_launch(void* const* d_in, const int* in_sizes, int n_in,
                              void* d_out, int out_size)
{
    const float* x     = (const float*)d_in[0];
    const float* gamma = (const float*)d_in[1];
    const float* beta  = (const float*)d_in[2];
    const float* w1    = (const float*)d_in[3];
    const float* b1    = (const float*)d_in[4];
    const float* wd    = (const float*)d_in[5];
    const float* bd    = (const float*)d_in[6];
    const float* wsm   = (const float*)d_in[7];
    const float* bs    = (const float*)d_in[8];
    const float* w2    = (const float*)d_in[9];
    const float* b2    = (const float*)d_in[10];
    float* out = (float*)d_out;

    cudaFuncSetAttribute(k1_ln_pw1, cudaFuncAttributeMaxDynamicSharedMemorySize, K1_SMEM);
    cudaFuncSetAttribute(k4_pw2,    cudaFuncAttributeMaxDynamicSharedMemorySize, K4_SMEM);

    k0_split<<<96, 256>>>(w1, w2);
    dim3 g1(NTILES, Bb);
    k1_ln_pw1<<<g1, 512, K1_SMEM>>>(x, gamma, beta, b1, wd, bd);
    dim3 g3(Bb, 32);
    k3_scale<<<g3, 256>>>(wsm, bs);
    dim3 g4(Ll / 64, Bb);
    k4_pw2<<<g4, 256, K4_SMEM>>>(x, b2, out);
}

// round 9
// speedup vs baseline: 13.5331x; 1.2897x over previous
#include <cuda_runtime.h>
#include <cuda_bf16.h>
#include <math.h>
#include <stdint.h>

#define Bb 16
#define Cc 256
#define CC2 512
#define Ll 8192
#define EPSV 1e-5f
#define TLI1 30
#define NT1 274              // ceil(8192/30)

// scratch
__device__ float g_gate[Bb * Cc * Ll];
__device__ float g_pool[Bb * Cc];
__device__ float g_scale[Bb * Cc];
// weights pre-packed as mma.m16n8k16 A-fragments:
//   index = (p * MT + mt) * 32 + lane, uint4 = {a0,a1,a2,a3}
__device__ uint4 g_w1f[16384], g_w1fl[16384];   // MT=32 (M=512), 16 panels
__device__ uint4 g_w2f[8192],  g_w2fl[8192];    // MT=16 (M=256), 16 panels

// ---------------- helpers ----------------
__device__ __forceinline__ uint32_t smem_u32(const void* p) {
    uint32_t a;
    asm("{ .reg .u64 t; cvta.to.shared.u64 t, %1; cvt.u32.u64 %0, t; }" : "=r"(a) : "l"(p));
    return a;
}
__device__ __forceinline__ void ldsm4(uint32_t* r, uint32_t addr) {
    asm volatile("ldmatrix.sync.aligned.m8n8.x4.shared.b16 {%0,%1,%2,%3}, [%4];"
        : "=r"(r[0]), "=r"(r[1]), "=r"(r[2]), "=r"(r[3]) : "r"(addr));
}
__device__ __forceinline__ void mma16816(float* c, const uint32_t* a, const uint32_t* b) {
    asm volatile("mma.sync.aligned.m16n8k16.row.col.f32.bf16.bf16.f32 "
        "{%0,%1,%2,%3}, {%4,%5,%6,%7}, {%8,%9}, {%0,%1,%2,%3};"
        : "+f"(c[0]), "+f"(c[1]), "+f"(c[2]), "+f"(c[3])
        : "r"(a[0]), "r"(a[1]), "r"(a[2]), "r"(a[3]), "r"(b[0]), "r"(b[1]));
}
__device__ __forceinline__ void bf16_split(float v, unsigned short* hi, unsigned short* lo) {
    __nv_bfloat16 h = __float2bfloat16(v);
    __nv_bfloat16 l = __float2bfloat16(v - __bfloat162float(h));
    *hi = *reinterpret_cast<unsigned short*>(&h);
    *lo = *reinterpret_cast<unsigned short*>(&l);
}
__device__ __forceinline__ uint32_t pack_hi2(float v0, float v1, uint32_t* lo) {
    unsigned short h0, h1, l0, l1;
    bf16_split(v0, &h0, &l0);
    bf16_split(v1, &h1, &l1);
    *lo = (uint32_t)l0 | ((uint32_t)l1 << 16);
    return (uint32_t)h0 | ((uint32_t)h1 << 16);
}
// B-tile byte offset: row l (n dim), channel c (k dim), swizzled for ldmatrix.
__device__ __forceinline__ uint32_t bswz(int l, int c) {
    return (uint32_t)(l * 512 + ((((c >> 3) ^ (l & 7)) << 4) | ((c & 7) * 2)));
}
// z staging word offset with XOR swizzle (k4)
__device__ __forceinline__ int zswz(int m, int l) {
    return m * 64 + (l ^ ((m & 7) << 3));
}

// ---------------------------------------------------------------------------
// K0: pack weights into mma A-fragment layout (hi/lo split); zero g_pool
// ---------------------------------------------------------------------------
__global__ __launch_bounds__(256) void k0_split(const float* __restrict__ w1,
                                                const float* __restrict__ w2)
{
    int idx = blockIdx.x * 256 + threadIdx.x;
    if (idx < Bb * Cc) g_pool[idx] = 0.f;

    if (idx < 16384) {                 // w1 fragments: MT=32
        int p = idx >> 10, rem = idx & 1023;
        int mt = rem >> 5, lane = rem & 31;
        int r = mt * 16 + (lane >> 2);
        int c = p * 16 + (lane & 3) * 2;
        const float* A = w1;
        uint4 hi, lo;
        hi.x = pack_hi2(A[r * Cc + c],           A[r * Cc + c + 1],           &lo.x);
        hi.y = pack_hi2(A[(r + 8) * Cc + c],     A[(r + 8) * Cc + c + 1],     &lo.y);
        hi.z = pack_hi2(A[r * Cc + c + 8],       A[r * Cc + c + 9],           &lo.z);
        hi.w = pack_hi2(A[(r + 8) * Cc + c + 8], A[(r + 8) * Cc + c + 9],     &lo.w);
        g_w1f[idx] = hi;  g_w1fl[idx] = lo;
    } else if (idx < 24576) {          // w2 fragments: MT=16
        int i2 = idx - 16384;
        int p = i2 >> 9, rem = i2 & 511;
        int mt = rem >> 5, lane = rem & 31;
        int r = mt * 16 + (lane >> 2);
        int c = p * 16 + (lane & 3) * 2;
        const float* A = w2;
        uint4 hi, lo;
        hi.x = pack_hi2(A[r * Cc + c],           A[r * Cc + c + 1],           &lo.x);
        hi.y = pack_hi2(A[(r + 8) * Cc + c],     A[(r + 8) * Cc + c + 1],     &lo.y);
        hi.z = pack_hi2(A[r * Cc + c + 8],       A[r * Cc + c + 9],           &lo.z);
        hi.w = pack_hi2(A[(r + 8) * Cc + c + 8], A[(r + 8) * Cc + c + 9],     &lo.w);
        g_w2f[i2] = hi;   g_w2fl[i2] = lo;
    }
}

// ---------------------------------------------------------------------------
// K1: LN + pw1 (M=512, N=32) + register dwconv + gate + fused pool
// 256 threads, 2 CTAs/SM. smem: B hi [0,16K) lo [16K,32K);
// red2 [32K,+2K) (aliased as redm later); stat [34K+768,+256)
// ---------------------------------------------------------------------------
#define K1_B    0
#define K1_RED  32768
#define K1_STAT 34816
#define K1_SMEM 35072

__global__ __launch_bounds__(256, 2) void k1_ln_pw1(
    const float* __restrict__ x, const float* __restrict__ gamma,
    const float* __restrict__ beta, const float* __restrict__ b1,
    const float* __restrict__ wd, const float* __restrict__ bd_)
{
    extern __shared__ char sm[];
    float* red2 = (float*)(sm + K1_RED);
    float* stat = (float*)(sm + K1_STAT);
    const uint32_t smb = smem_u32(sm);
    const int b    = blockIdx.y;
    const int tile = blockIdx.x;
    const int l0   = tile * TLI1 - 1;   // global l of local col 0
    const int tid  = threadIdx.x;
    const int w    = tid >> 5, lane = tid & 31;

    // ---- LN stats: warp w sums channels {w, w+8, ...} for column lane ----
    {
        int lg = l0 + lane;
        bool ok = (lg >= 0 && lg < Ll);
        float s = 0.f, sq = 0.f;
        if (ok) {
            const float* xp = x + (size_t)(b * Cc + w) * Ll + lg;
            for (int c = 0; c < 32; c++) {
                float v = __ldg(xp + (size_t)c * 8 * Ll);
                s += v; sq += v * v;
            }
        }
        red2[w * 32 + lane]       = s;
        red2[256 + w * 32 + lane] = sq;
    }
    __syncthreads();
    if (tid < 32) {
        float s = 0.f, sq = 0.f;
        #pragma unroll
        for (int k = 0; k < 8; k++) { s += red2[k * 32 + tid]; sq += red2[256 + k * 32 + tid]; }
        float mu = s * (1.f / Cc);
        float var = sq * (1.f / Cc) - mu * mu;
        stat[tid]      = mu;
        stat[32 + tid] = rsqrtf(var + EPSV);
    }
    __syncthreads();

    // ---- normalize (2nd x read, L2 hit) + bf16 split -> B tile [32 l][256 c]
    for (int i = tid; i < 128 * 32; i += 256) {
        int cp = i >> 5, l = i & 31;
        int c = cp * 2;
        int lg = l0 + l;
        bool ok = (lg >= 0 && lg < Ll);
        float x0 = ok ? __ldg(&x[(size_t)(b * Cc + c) * Ll + lg]) : 0.f;
        float x1 = ok ? __ldg(&x[(size_t)(b * Cc + c + 1) * Ll + lg]) : 0.f;
        float mu = stat[l], rs = stat[32 + l];
        float v0 = (x0 - mu) * rs * __ldg(&gamma[c]) + __ldg(&beta[c]);
        float v1 = (x1 - mu) * rs * __ldg(&gamma[c + 1]) + __ldg(&beta[c + 1]);
        uint32_t lop;
        uint32_t hip = pack_hi2(v0, v1, &lop);
        uint32_t by = bswz(l, c);
        *(uint32_t*)(sm + K1_B + by)         = hip;
        *(uint32_t*)(sm + K1_B + 16384 + by) = lop;
    }
    __syncthreads();

    // ---- GEMM: M=512, N=32, K=256. warp w owns mt {w, w+8, w+16, w+24} ----
    const int lr  = lane & 7;
    const int gb0 = (lane >> 3) & 1;
    const int gb1 = lane >> 4;
    uint32_t bBase[2];
    #pragma unroll
    for (int bp = 0; bp < 2; bp++)
        bBase[bp] = smb + K1_B + (uint32_t)((bp * 16 + gb1 * 8 + lr) * 512);

    float acc[4][4][4];
    #pragma unroll
    for (int mi = 0; mi < 4; mi++)
        #pragma unroll
        for (int nt = 0; nt < 4; nt++)
            #pragma unroll
            for (int q = 0; q < 4; q++) acc[mi][nt][q] = 0.f;

    const uint4* AH[4];
    const uint4* AL[4];
    #pragma unroll
    for (int mi = 0; mi < 4; mi++) {
        int mt = w + mi * 8;
        AH[mi] = g_w1f  + mt * 32 + lane;
        AL[mi] = g_w1fl + mt * 32 + lane;
    }

    #pragma unroll 4
    for (int p = 0; p < 16; ++p) {
        uint32_t kx = (uint32_t)(((p * 2 + gb0) ^ lr) << 4);
        uint32_t Bh[8], Bl[8];
        ldsm4(&Bh[0], bBase[0] + kx);
        ldsm4(&Bh[4], bBase[1] + kx);
        ldsm4(&Bl[0], bBase[0] + 16384 + kx);
        ldsm4(&Bl[4], bBase[1] + 16384 + kx);
        #pragma unroll
        for (int mi = 0; mi < 4; mi++) {
            uint4 ah = __ldg(AH[mi] + p * 1024);
            uint4 al = __ldg(AL[mi] + p * 1024);
            #pragma unroll
            for (int nt = 0; nt < 4; nt++) {
                mma16816(acc[mi][nt], (const uint32_t*)&ah, &Bh[nt * 2]);
                mma16816(acc[mi][nt], (const uint32_t*)&ah, &Bl[nt * 2]);
                mma16816(acc[mi][nt], (const uint32_t*)&al, &Bh[nt * 2]);
            }
        }
    }

    // ---- register epilogue: bias + dwconv (shfl halo) + gate + pool ----
    float* redm = red2;                 // alias (LN reductions long dead)
    const int j  = lane & 3;
    const int rl = lane >> 2;
    const int srcL = (lane & ~3) | ((j + 3) & 3);   // takes from lane j-1 (mod 4)
    const int srcR = (lane & ~3) | ((j + 1) & 3);   // takes from lane j+1 (mod 4)

    #pragma unroll
    for (int pair = 0; pair < 2; ++pair) {
        #pragma unroll
        for (int q = 0; q < 2; ++q) {
            const int m  = (w + pair * 8) * 16 + q * 8 + rl;
            const int m2 = m + Cc;
            const float biA = __ldg(&b1[m]);
            const float biB = __ldg(&b1[m2]);
            float zA0[4], zA1[4], zB0[4], zB1[4];
            #pragma unroll
            for (int nt = 0; nt < 4; nt++) {
                zA0[nt] = acc[pair][nt][q * 2]     + biA;
                zA1[nt] = acc[pair][nt][q * 2 + 1] + biA;
                zB0[nt] = acc[pair + 2][nt][q * 2]     + biB;
                zB1[nt] = acc[pair + 2][nt][q * 2 + 1] + biB;
            }
            // halo rotations (uniform shfls, no divergence)
            float rA1[4], rA0[4], rB1[4], rB0[4];
            #pragma unroll
            for (int nt = 0; nt < 4; nt++) {
                rA1[nt] = __shfl_sync(0xFFFFFFFFu, zA1[nt], srcL);
                rA0[nt] = __shfl_sync(0xFFFFFFFFu, zA0[nt], srcR);
                rB1[nt] = __shfl_sync(0xFFFFFFFFu, zB1[nt], srcL);
                rB0[nt] = __shfl_sync(0xFFFFFFFFu, zB0[nt], srcR);
            }
            const float wa0 = __ldg(&wd[m * 3 + 0]),  wa1 = __ldg(&wd[m * 3 + 1]),
                        wa2 = __ldg(&wd[m * 3 + 2]),  ba  = __ldg(&bd_[m]);
            const float wb0 = __ldg(&wd[m2 * 3 + 0]), wb1 = __ldg(&wd[m2 * 3 + 1]),
                        wb2 = __ldg(&wd[m2 * 3 + 2]), bb  = __ldg(&bd_[m2]);
            float* orow = g_gate + (size_t)(b * Cc + m) * Ll;
            float psum = 0.f;
            #pragma unroll
            for (int nt = 0; nt < 4; nt++) {
                #pragma unroll
                for (int e = 0; e < 2; e++) {
                    int co = nt * 8 + 2 * j + e;
                    if (co >= 1 && co <= 30) {
                        int lg = l0 + co;
                        if (lg >= 0 && lg < Ll) {
                            float am1, ac, ap1, bm1, bc, bp1;
                            if (e == 0) {
                                am1 = (j == 0) ? (nt > 0 ? rA1[nt - 1] : 0.f) : rA1[nt];
                                bm1 = (j == 0) ? (nt > 0 ? rB1[nt - 1] : 0.f) : rB1[nt];
                                ac = zA0[nt]; ap1 = zA1[nt];
                                bc = zB0[nt]; bp1 = zB1[nt];
                            } else {
                                am1 = zA0[nt]; ac = zA1[nt];
                                bm1 = zB0[nt]; bc = zB1[nt];
                                ap1 = (j == 3) ? (nt < 3 ? rA0[nt + 1] : 0.f) : rA0[nt];
                                bp1 = (j == 3) ? (nt < 3 ? rB0[nt + 1] : 0.f) : rB0[nt];
                            }
                            if (lg - 1 < 0)   { am1 = 0.f; bm1 = 0.f; }
                            if (lg + 1 >= Ll) { ap1 = 0.f; bp1 = 0.f; }
                            float d1 = wa0 * am1 + wa1 * ac + wa2 * ap1 + ba;
                            float d2 = wb0 * bm1 + wb1 * bc + wb2 * bp1 + bb;
                            float g = d1 * d2;
                            orow[lg] = g;
                            psum += g;
                        }
                    }
                }
            }
            // quad reduce (lanes 4r..4r+3 share row m)
            psum += __shfl_xor_sync(0xFFFFFFFFu, psum, 1);
            psum += __shfl_xor_sync(0xFFFFFFFFu, psum, 2);
            if (j == 0) redm[m] = psum;
        }
    }
    __syncthreads();
    if (tid < 256) {
        float v = redm[tid];
        if (v != 0.f) atomicAdd(&g_pool[b * Cc + tid], v * (1.f / Ll));
    }
}

// ---------------------------------------------------------------------------
// K3: SCA scale = sigmoid(ws @ pool + bs); one warp per output
// ---------------------------------------------------------------------------
__global__ __launch_bounds__(256) void k3_scale(
    const float* __restrict__ ws, const float* __restrict__ bs)
{
    __shared__ float sp[Cc];
    const int b = blockIdx.x;
    const int w = threadIdx.x >> 5, lane = threadIdx.x & 31;
    const int c = blockIdx.y * 8 + w;
    sp[threadIdx.x] = g_pool[b * Cc + threadIdx.x];
    __syncthreads();
    const float4* wr = (const float4*)(ws + c * Cc);
    const float4* pp = (const float4*)sp;
    float4 a0 = __ldg(&wr[lane * 2]), a1 = __ldg(&wr[lane * 2 + 1]);
    float4 p0 = pp[lane * 2], p1 = pp[lane * 2 + 1];
    float s = a0.x * p0.x + a0.y * p0.y + a0.z * p0.z + a0.w * p0.w
            + a1.x * p1.x + a1.y * p1.y + a1.z * p1.z + a1.w * p1.w;
    #pragma unroll
    for (int o = 16; o; o >>= 1) s += __shfl_xor_sync(0xFFFFFFFFu, s, o);
    if (lane == 0)
        g_scale[b * Cc + c] = 1.f / (1.f + expf(-(s + __ldg(&bs[c]))));
}

// ---------------------------------------------------------------------------
// K4: pw2 (barrier-free mainloop) + bias + residual. 256 thr, 2 CTAs/SM.
// smem: [0,64K) B hi|lo (later z)
// ---------------------------------------------------------------------------
#define K4_B 0
#define K4_SMEM 65536

__global__ __launch_bounds__(256, 2) void k4_pw2(
    const float* __restrict__ x, const float* __restrict__ b2,
    float* __restrict__ out)
{
    extern __shared__ char sm[];
    const uint32_t smb = smem_u32(sm);
    const int b = blockIdx.y, tile = blockIdx.x, tid = threadIdx.x;
    const int w = tid >> 5, lane = tid & 31;
    const int l0 = tile * 64;

    // ---- B tile: gate*scale -> bf16 split ----
    for (int i = tid; i < 128 * 64; i += 256) {
        int cp = i >> 6, l = i & 63;
        int c = cp * 2;
        float v0 = g_gate[(size_t)(b * Cc + c) * Ll + l0 + l] * __ldg(&g_scale[b * Cc + c]);
        float v1 = g_gate[(size_t)(b * Cc + c + 1) * Ll + l0 + l] * __ldg(&g_scale[b * Cc + c + 1]);
        uint32_t lop;
        uint32_t hip = pack_hi2(v0, v1, &lop);
        uint32_t by = bswz(l, c);
        *(uint32_t*)(sm + K4_B + by)         = hip;
        *(uint32_t*)(sm + K4_B + 32768 + by) = lop;
    }
    __syncthreads();

    const int lr  = lane & 7;
    const int gb0 = (lane >> 3) & 1;
    const int gb1 = lane >> 4;
    uint32_t bBase[4];
    #pragma unroll
    for (int bp = 0; bp < 4; bp++)
        bBase[bp] = smb + K4_B + (uint32_t)((bp * 16 + gb1 * 8 + lr) * 512);

    float acc[2][8][4];
    #pragma unroll
    for (int mt = 0; mt < 2; mt++)
        #pragma unroll
        for (int nt = 0; nt < 8; nt++)
            #pragma unroll
            for (int q = 0; q < 4; q++) acc[mt][nt][q] = 0.f;

    const uint4* A0H = g_w2f  + w * 32 + lane;          // mt = w
    const uint4* A0L = g_w2fl + w * 32 + lane;
    const uint4* A1H = g_w2f  + (8 + w) * 32 + lane;    // mt = 8 + w
    const uint4* A1L = g_w2fl + (8 + w) * 32 + lane;

    #pragma unroll 4
    for (int p = 0; p < 16; ++p) {
        uint4 a0h = __ldg(A0H + p * 512);
        uint4 a0l = __ldg(A0L + p * 512);
        uint4 a1h = __ldg(A1H + p * 512);
        uint4 a1l = __ldg(A1L + p * 512);
        uint32_t kx = (uint32_t)(((p * 2 + gb0) ^ lr) << 4);
        #pragma unroll
        for (int bp = 0; bp < 4; bp++) {
            uint32_t Bh[4], Bl[4];
            ldsm4(Bh, bBase[bp] + kx);
            ldsm4(Bl, bBase[bp] + 32768 + kx);
            #pragma unroll
            for (int q = 0; q < 2; q++) {
                int nt = bp * 2 + q;
                mma16816(acc[0][nt], (const uint32_t*)&a0h, &Bh[q * 2]);
                mma16816(acc[0][nt], (const uint32_t*)&a0h, &Bl[q * 2]);
                mma16816(acc[0][nt], (const uint32_t*)&a0l, &Bh[q * 2]);
                mma16816(acc[1][nt], (const uint32_t*)&a1h, &Bh[q * 2]);
                mma16816(acc[1][nt], (const uint32_t*)&a1h, &Bl[q * 2]);
                mma16816(acc[1][nt], (const uint32_t*)&a1l, &Bh[q * 2]);
            }
        }
    }
    __syncthreads();   // B reads done before aliasing as z

    // stage z (XOR-swizzled), aliases B region
    float* zb = (float*)(sm + K4_B);
    #pragma unroll
    for (int mt = 0; mt < 2; mt++) {
        int r = mt * 128 + w * 16 + (lane >> 2);
        #pragma unroll
        for (int nt = 0; nt < 8; nt++) {
            int c = nt * 8 + (lane & 3) * 2;
            int w0 = zswz(r, c), w1i = zswz(r + 8, c);
            zb[w0]      = acc[mt][nt][0];
            zb[w0 + 1]  = acc[mt][nt][1];
            zb[w1i]     = acc[mt][nt][2];
            zb[w1i + 1] = acc[mt][nt][3];
        }
    }
    __syncthreads();

    // out = z + b2 + x   (coalesced float4, de-swizzled read)
    for (int i = tid; i < Cc * 16; i += 256) {
        int m = i >> 4, lq = i & 15;
        int slot = lq ^ ((m & 7) << 1);
        float4 zv = *(const float4*)(zb + m * 64 + slot * 4);
        float bias = __ldg(&b2[m]);
        const float* xr = x + (size_t)(b * Cc + m) * Ll + l0 + lq * 4;
        float4 xv = *(const float4*)xr;
        float4 ov;
        ov.x = zv.x + bias + xv.x;
        ov.y = zv.y + bias + xv.y;
        ov.z = zv.z + bias + xv.z;
        ov.w = zv.w + bias + xv.w;
        *(float4*)(out + (size_t)(b * Cc + m) * Ll + l0 + lq * 4) = ov;
    }
}

// ---------------------------------------------------------------------------
extern "C" void kernel_launch(void* const* d_in, const int* in_sizes, int n_in,
                              void* d_out, int out_size)
{
    const float* x     = (const float*)d_in[0];
    const float* gamma = (const float*)d_in[1];
    const float* beta  = (const float*)d_in[2];
    const float* w1    = (const float*)d_in[3];
    const float* b1    = (const float*)d_in[4];
    const float* wd    = (const float*)d_in[5];
    const float* bd    = (const float*)d_in[6];
    const float* wsm   = (const float*)d_in[7];
    const float* bs    = (const float*)d_in[8];
    const float* w2    = (const float*)d_in[9];
    const float* b2    = (const float*)d_in[10];
    float* out = (float*)d_out;

    cudaFuncSetAttribute(k4_pw2, cudaFuncAttributeMaxDynamicSharedMemorySize, K4_SMEM);

    k0_split<<<96, 256>>>(w1, w2);
    dim3 g1(NT1, Bb);
    k1_ln_pw1<<<g1, 256, K1_SMEM>>>(x, gamma, beta, b1, wd, bd);
    dim3 g3(Bb, 32);
    k3_scale<<<g3, 256>>>(wsm, bs);
    dim3 g4(Ll / 64, Bb);
    k4_pw2<<<g4, 256, K4_SMEM>>>(x, b2, out);
}

// round 10
// speedup vs baseline: 13.8539x; 1.0237x over previous
#include <cuda_runtime.h>
#include <cuda_bf16.h>
#include <math.h>
#include <stdint.h>

#define Bb 16
#define Cc 256
#define CC2 512
#define Ll 8192
#define EPSV 1e-5f
#define TLI1 30
#define NT1 274              // ceil(8192/30)

// scratch
__device__ float g_gate[Bb * Cc * Ll];
__device__ float g_pool[Bb * Cc];
__device__ float g_scale[Bb * Cc];
// weights pre-packed as mma.m16n8k16 A-fragments:
//   index = (p * MT + mt) * 32 + lane, uint4 = {a0,a1,a2,a3}
__device__ uint4 g_w1f[16384], g_w1fl[16384];   // MT=32 (M=512), 16 panels
__device__ uint4 g_w2f[8192],  g_w2fl[8192];    // MT=16 (M=256), 16 panels

// ---------------- helpers ----------------
__device__ __forceinline__ uint32_t smem_u32(const void* p) {
    uint32_t a;
    asm("{ .reg .u64 t; cvta.to.shared.u64 t, %1; cvt.u32.u64 %0, t; }" : "=r"(a) : "l"(p));
    return a;
}
__device__ __forceinline__ void ldsm4(uint32_t* r, uint32_t addr) {
    asm volatile("ldmatrix.sync.aligned.m8n8.x4.shared.b16 {%0,%1,%2,%3}, [%4];"
        : "=r"(r[0]), "=r"(r[1]), "=r"(r[2]), "=r"(r[3]) : "r"(addr));
}
__device__ __forceinline__ void mma16816(float* c, const uint32_t* a, const uint32_t* b) {
    asm volatile("mma.sync.aligned.m16n8k16.row.col.f32.bf16.bf16.f32 "
        "{%0,%1,%2,%3}, {%4,%5,%6,%7}, {%8,%9}, {%0,%1,%2,%3};"
        : "+f"(c[0]), "+f"(c[1]), "+f"(c[2]), "+f"(c[3])
        : "r"(a[0]), "r"(a[1]), "r"(a[2]), "r"(a[3]), "r"(b[0]), "r"(b[1]));
}
__device__ __forceinline__ void bf16_split(float v, unsigned short* hi, unsigned short* lo) {
    __nv_bfloat16 h = __float2bfloat16(v);
    __nv_bfloat16 l = __float2bfloat16(v - __bfloat162float(h));
    *hi = *reinterpret_cast<unsigned short*>(&h);
    *lo = *reinterpret_cast<unsigned short*>(&l);
}
__device__ __forceinline__ uint32_t pack_hi2(float v0, float v1, uint32_t* lo) {
    unsigned short h0, h1, l0, l1;
    bf16_split(v0, &h0, &l0);
    bf16_split(v1, &h1, &l1);
    *lo = (uint32_t)l0 | ((uint32_t)l1 << 16);
    return (uint32_t)h0 | ((uint32_t)h1 << 16);
}
// B-tile byte offset: row l (n dim), channel c (k dim), swizzled for ldmatrix.
__device__ __forceinline__ uint32_t bswz(int l, int c) {
    return (uint32_t)(l * 512 + ((((c >> 3) ^ (l & 7)) << 4) | ((c & 7) * 2)));
}

// ---------------------------------------------------------------------------
// K0: pack weights into mma A-fragment layout (hi/lo split); zero g_pool
// ---------------------------------------------------------------------------
__global__ __launch_bounds__(256) void k0_split(const float* __restrict__ w1,
                                                const float* __restrict__ w2)
{
    int idx = blockIdx.x * 256 + threadIdx.x;
    if (idx < Bb * Cc) g_pool[idx] = 0.f;

    if (idx < 16384) {                 // w1 fragments: MT=32
        int p = idx >> 10, rem = idx & 1023;
        int mt = rem >> 5, lane = rem & 31;
        int r = mt * 16 + (lane >> 2);
        int c = p * 16 + (lane & 3) * 2;
        const float* A = w1;
        uint4 hi, lo;
        hi.x = pack_hi2(A[r * Cc + c],           A[r * Cc + c + 1],           &lo.x);
        hi.y = pack_hi2(A[(r + 8) * Cc + c],     A[(r + 8) * Cc + c + 1],     &lo.y);
        hi.z = pack_hi2(A[r * Cc + c + 8],       A[r * Cc + c + 9],           &lo.z);
        hi.w = pack_hi2(A[(r + 8) * Cc + c + 8], A[(r + 8) * Cc + c + 9],     &lo.w);
        g_w1f[idx] = hi;  g_w1fl[idx] = lo;
    } else if (idx < 24576) {          // w2 fragments: MT=16
        int i2 = idx - 16384;
        int p = i2 >> 9, rem = i2 & 511;
        int mt = rem >> 5, lane = rem & 31;
        int r = mt * 16 + (lane >> 2);
        int c = p * 16 + (lane & 3) * 2;
        const float* A = w2;
        uint4 hi, lo;
        hi.x = pack_hi2(A[r * Cc + c],           A[r * Cc + c + 1],           &lo.x);
        hi.y = pack_hi2(A[(r + 8) * Cc + c],     A[(r + 8) * Cc + c + 1],     &lo.y);
        hi.z = pack_hi2(A[r * Cc + c + 8],       A[r * Cc + c + 9],           &lo.z);
        hi.w = pack_hi2(A[(r + 8) * Cc + c + 8], A[(r + 8) * Cc + c + 9],     &lo.w);
        g_w2f[i2] = hi;   g_w2fl[i2] = lo;
    }
}

// ---------------------------------------------------------------------------
// K1: LN + pw1 (M=512, N=32) + register dwconv + gate + fused pool
// 256 threads, 2 CTAs/SM. smem: B hi [0,16K) lo [16K,32K);
// red2 [32K,+2K) (aliased as redm later); stat [34K,+256)
// ---------------------------------------------------------------------------
#define K1_B    0
#define K1_RED  32768
#define K1_STAT 34816
#define K1_SMEM 35072

__global__ __launch_bounds__(256, 2) void k1_ln_pw1(
    const float* __restrict__ x, const float* __restrict__ gamma,
    const float* __restrict__ beta, const float* __restrict__ b1,
    const float* __restrict__ wd, const float* __restrict__ bd_)
{
    extern __shared__ char sm[];
    float* red2 = (float*)(sm + K1_RED);
    float* stat = (float*)(sm + K1_STAT);
    const uint32_t smb = smem_u32(sm);
    const int b    = blockIdx.y;
    const int tile = blockIdx.x;
    const int l0   = tile * TLI1 - 1;   // global l of local col 0
    const int tid  = threadIdx.x;
    const int w    = tid >> 5, lane = tid & 31;

    // ---- LN stats: warp w sums channels {w, w+8, ...} for column lane ----
    {
        int lg = l0 + lane;
        bool ok = (lg >= 0 && lg < Ll);
        float s = 0.f, sq = 0.f;
        if (ok) {
            const float* xp = x + (size_t)(b * Cc + w) * Ll + lg;
            for (int c = 0; c < 32; c++) {
                float v = __ldg(xp + (size_t)c * 8 * Ll);
                s += v; sq += v * v;
            }
        }
        red2[w * 32 + lane]       = s;
        red2[256 + w * 32 + lane] = sq;
    }
    __syncthreads();
    if (tid < 32) {
        float s = 0.f, sq = 0.f;
        #pragma unroll
        for (int k = 0; k < 8; k++) { s += red2[k * 32 + tid]; sq += red2[256 + k * 32 + tid]; }
        float mu = s * (1.f / Cc);
        float var = sq * (1.f / Cc) - mu * mu;
        stat[tid]      = mu;
        stat[32 + tid] = rsqrtf(var + EPSV);
    }
    __syncthreads();

    // ---- normalize (2nd x read, L2 hit) + bf16 split -> B tile [32 l][256 c]
    for (int i = tid; i < 128 * 32; i += 256) {
        int cp = i >> 5, l = i & 31;
        int c = cp * 2;
        int lg = l0 + l;
        bool ok = (lg >= 0 && lg < Ll);
        float x0 = ok ? __ldg(&x[(size_t)(b * Cc + c) * Ll + lg]) : 0.f;
        float x1 = ok ? __ldg(&x[(size_t)(b * Cc + c + 1) * Ll + lg]) : 0.f;
        float mu = stat[l], rs = stat[32 + l];
        float v0 = (x0 - mu) * rs * __ldg(&gamma[c]) + __ldg(&beta[c]);
        float v1 = (x1 - mu) * rs * __ldg(&gamma[c + 1]) + __ldg(&beta[c + 1]);
        uint32_t lop;
        uint32_t hip = pack_hi2(v0, v1, &lop);
        uint32_t by = bswz(l, c);
        *(uint32_t*)(sm + K1_B + by)         = hip;
        *(uint32_t*)(sm + K1_B + 16384 + by) = lop;
    }
    __syncthreads();

    // ---- GEMM: M=512, N=32, K=256. warp w owns mt {w, w+8, w+16, w+24} ----
    const int lr  = lane & 7;
    const int gb0 = (lane >> 3) & 1;
    const int gb1 = lane >> 4;
    uint32_t bBase[2];
    #pragma unroll
    for (int bp = 0; bp < 2; bp++)
        bBase[bp] = smb + K1_B + (uint32_t)((bp * 16 + gb1 * 8 + lr) * 512);

    float acc[4][4][4];
    #pragma unroll
    for (int mi = 0; mi < 4; mi++)
        #pragma unroll
        for (int nt = 0; nt < 4; nt++)
            #pragma unroll
            for (int q = 0; q < 4; q++) acc[mi][nt][q] = 0.f;

    const uint4* AH[4];
    const uint4* AL[4];
    #pragma unroll
    for (int mi = 0; mi < 4; mi++) {
        int mt = w + mi * 8;
        AH[mi] = g_w1f  + mt * 32 + lane;
        AL[mi] = g_w1fl + mt * 32 + lane;
    }

    #pragma unroll 4
    for (int p = 0; p < 16; ++p) {
        uint32_t kx = (uint32_t)(((p * 2 + gb0) ^ lr) << 4);
        uint32_t Bh[8], Bl[8];
        ldsm4(&Bh[0], bBase[0] + kx);
        ldsm4(&Bh[4], bBase[1] + kx);
        ldsm4(&Bl[0], bBase[0] + 16384 + kx);
        ldsm4(&Bl[4], bBase[1] + 16384 + kx);
        #pragma unroll
        for (int mi = 0; mi < 4; mi++) {
            uint4 ah = __ldg(AH[mi] + p * 1024);
            uint4 al = __ldg(AL[mi] + p * 1024);
            #pragma unroll
            for (int nt = 0; nt < 4; nt++) {
                mma16816(acc[mi][nt], (const uint32_t*)&ah, &Bh[nt * 2]);
                mma16816(acc[mi][nt], (const uint32_t*)&ah, &Bl[nt * 2]);
                mma16816(acc[mi][nt], (const uint32_t*)&al, &Bh[nt * 2]);
            }
        }
    }

    // ---- register epilogue: bias + dwconv (shfl halo) + gate + pool ----
    float* redm = red2;                 // alias (LN reductions long dead)
    const int j  = lane & 3;
    const int rl = lane >> 2;
    const int srcL = (lane & ~3) | ((j + 3) & 3);   // takes from lane j-1 (mod 4)
    const int srcR = (lane & ~3) | ((j + 1) & 3);   // takes from lane j+1 (mod 4)

    #pragma unroll
    for (int pair = 0; pair < 2; ++pair) {
        #pragma unroll
        for (int q = 0; q < 2; ++q) {
            const int m  = (w + pair * 8) * 16 + q * 8 + rl;
            const int m2 = m + Cc;
            const float biA = __ldg(&b1[m]);
            const float biB = __ldg(&b1[m2]);
            float zA0[4], zA1[4], zB0[4], zB1[4];
            #pragma unroll
            for (int nt = 0; nt < 4; nt++) {
                zA0[nt] = acc[pair][nt][q * 2]     + biA;
                zA1[nt] = acc[pair][nt][q * 2 + 1] + biA;
                zB0[nt] = acc[pair + 2][nt][q * 2]     + biB;
                zB1[nt] = acc[pair + 2][nt][q * 2 + 1] + biB;
            }
            float rA1[4], rA0[4], rB1[4], rB0[4];
            #pragma unroll
            for (int nt = 0; nt < 4; nt++) {
                rA1[nt] = __shfl_sync(0xFFFFFFFFu, zA1[nt], srcL);
                rA0[nt] = __shfl_sync(0xFFFFFFFFu, zA0[nt], srcR);
                rB1[nt] = __shfl_sync(0xFFFFFFFFu, zB1[nt], srcL);
                rB0[nt] = __shfl_sync(0xFFFFFFFFu, zB0[nt], srcR);
            }
            const float wa0 = __ldg(&wd[m * 3 + 0]),  wa1 = __ldg(&wd[m * 3 + 1]),
                        wa2 = __ldg(&wd[m * 3 + 2]),  ba  = __ldg(&bd_[m]);
            const float wb0 = __ldg(&wd[m2 * 3 + 0]), wb1 = __ldg(&wd[m2 * 3 + 1]),
                        wb2 = __ldg(&wd[m2 * 3 + 2]), bb  = __ldg(&bd_[m2]);
            float* orow = g_gate + (size_t)(b * Cc + m) * Ll;
            float psum = 0.f;
            #pragma unroll
            for (int nt = 0; nt < 4; nt++) {
                #pragma unroll
                for (int e = 0; e < 2; e++) {
                    int co = nt * 8 + 2 * j + e;
                    if (co >= 1 && co <= 30) {
                        int lg = l0 + co;
                        if (lg >= 0 && lg < Ll) {
                            float am1, ac, ap1, bm1, bc, bp1;
                            if (e == 0) {
                                am1 = (j == 0) ? (nt > 0 ? rA1[nt - 1] : 0.f) : rA1[nt];
                                bm1 = (j == 0) ? (nt > 0 ? rB1[nt - 1] : 0.f) : rB1[nt];
                                ac = zA0[nt]; ap1 = zA1[nt];
                                bc = zB0[nt]; bp1 = zB1[nt];
                            } else {
                                am1 = zA0[nt]; ac = zA1[nt];
                                bm1 = zB0[nt]; bc = zB1[nt];
                                ap1 = (j == 3) ? (nt < 3 ? rA0[nt + 1] : 0.f) : rA0[nt];
                                bp1 = (j == 3) ? (nt < 3 ? rB0[nt + 1] : 0.f) : rB0[nt];
                            }
                            if (lg - 1 < 0)   { am1 = 0.f; bm1 = 0.f; }
                            if (lg + 1 >= Ll) { ap1 = 0.f; bp1 = 0.f; }
                            float d1 = wa0 * am1 + wa1 * ac + wa2 * ap1 + ba;
                            float d2 = wb0 * bm1 + wb1 * bc + wb2 * bp1 + bb;
                            float g = d1 * d2;
                            orow[lg] = g;
                            psum += g;
                        }
                    }
                }
            }
            psum += __shfl_xor_sync(0xFFFFFFFFu, psum, 1);
            psum += __shfl_xor_sync(0xFFFFFFFFu, psum, 2);
            if (j == 0) redm[m] = psum;
        }
    }
    __syncthreads();
    if (tid < 256) {
        float v = redm[tid];
        if (v != 0.f) atomicAdd(&g_pool[b * Cc + tid], v * (1.f / Ll));
    }
}

// ---------------------------------------------------------------------------
// K3: SCA scale = sigmoid(ws @ pool + bs); one warp per output
// ---------------------------------------------------------------------------
__global__ __launch_bounds__(256) void k3_scale(
    const float* __restrict__ ws, const float* __restrict__ bs)
{
    __shared__ float sp[Cc];
    const int b = blockIdx.x;
    const int w = threadIdx.x >> 5, lane = threadIdx.x & 31;
    const int c = blockIdx.y * 8 + w;
    sp[threadIdx.x] = g_pool[b * Cc + threadIdx.x];
    __syncthreads();
    const float4* wr = (const float4*)(ws + c * Cc);
    const float4* pp = (const float4*)sp;
    float4 a0 = __ldg(&wr[lane * 2]), a1 = __ldg(&wr[lane * 2 + 1]);
    float4 p0 = pp[lane * 2], p1 = pp[lane * 2 + 1];
    float s = a0.x * p0.x + a0.y * p0.y + a0.z * p0.z + a0.w * p0.w
            + a1.x * p1.x + a1.y * p1.y + a1.z * p1.z + a1.w * p1.w;
    #pragma unroll
    for (int o = 16; o; o >>= 1) s += __shfl_xor_sync(0xFFFFFFFFu, s, o);
    if (lane == 0)
        g_scale[b * Cc + c] = 1.f / (1.f + expf(-(s + __ldg(&bs[c]))));
}

// ---------------------------------------------------------------------------
// K4: pw2 (M=256, N=32) + bias + residual, register epilogue.
// 256 threads, 3 CTAs/SM target. smem: B hi [0,16K) lo [16K,32K)
// ---------------------------------------------------------------------------
#define K4_B 0
#define K4_SMEM 32768

__global__ __launch_bounds__(256, 3) void k4_pw2(
    const float* __restrict__ x, const float* __restrict__ b2,
    float* __restrict__ out)
{
    extern __shared__ char sm[];
    const uint32_t smb = smem_u32(sm);
    const int b = blockIdx.y, tile = blockIdx.x, tid = threadIdx.x;
    const int w = tid >> 5, lane = tid & 31;
    const int l0 = tile * 32;

    // ---- B tile: gate*scale -> bf16 split [32 l][256 c] ----
    for (int i = tid; i < 128 * 32; i += 256) {
        int cp = i >> 5, l = i & 31;
        int c = cp * 2;
        float v0 = g_gate[(size_t)(b * Cc + c) * Ll + l0 + l] * __ldg(&g_scale[b * Cc + c]);
        float v1 = g_gate[(size_t)(b * Cc + c + 1) * Ll + l0 + l] * __ldg(&g_scale[b * Cc + c + 1]);
        uint32_t lop;
        uint32_t hip = pack_hi2(v0, v1, &lop);
        uint32_t by = bswz(l, c);
        *(uint32_t*)(sm + K4_B + by)         = hip;
        *(uint32_t*)(sm + K4_B + 16384 + by) = lop;
    }
    __syncthreads();

    const int lr  = lane & 7;
    const int gb0 = (lane >> 3) & 1;
    const int gb1 = lane >> 4;
    uint32_t bBase[2];
    #pragma unroll
    for (int bp = 0; bp < 2; bp++)
        bBase[bp] = smb + K4_B + (uint32_t)((bp * 16 + gb1 * 8 + lr) * 512);

    float acc[2][4][4];
    #pragma unroll
    for (int mt = 0; mt < 2; mt++)
        #pragma unroll
        for (int nt = 0; nt < 4; nt++)
            #pragma unroll
            for (int q = 0; q < 4; q++) acc[mt][nt][q] = 0.f;

    const uint4* A0H = g_w2f  + w * 32 + lane;          // mt = w
    const uint4* A0L = g_w2fl + w * 32 + lane;
    const uint4* A1H = g_w2f  + (8 + w) * 32 + lane;    // mt = 8 + w
    const uint4* A1L = g_w2fl + (8 + w) * 32 + lane;

    #pragma unroll 4
    for (int p = 0; p < 16; ++p) {
        uint32_t kx = (uint32_t)(((p * 2 + gb0) ^ lr) << 4);
        uint32_t Bh[8], Bl[8];
        ldsm4(&Bh[0], bBase[0] + kx);
        ldsm4(&Bh[4], bBase[1] + kx);
        ldsm4(&Bl[0], bBase[0] + 16384 + kx);
        ldsm4(&Bl[4], bBase[1] + 16384 + kx);
        uint4 a0h = __ldg(A0H + p * 512);
        uint4 a0l = __ldg(A0L + p * 512);
        uint4 a1h = __ldg(A1H + p * 512);
        uint4 a1l = __ldg(A1L + p * 512);
        #pragma unroll
        for (int nt = 0; nt < 4; nt++) {
            mma16816(acc[0][nt], (const uint32_t*)&a0h, &Bh[nt * 2]);
            mma16816(acc[0][nt], (const uint32_t*)&a0h, &Bl[nt * 2]);
            mma16816(acc[0][nt], (const uint32_t*)&a0l, &Bh[nt * 2]);
            mma16816(acc[1][nt], (const uint32_t*)&a1h, &Bh[nt * 2]);
            mma16816(acc[1][nt], (const uint32_t*)&a1h, &Bl[nt * 2]);
            mma16816(acc[1][nt], (const uint32_t*)&a1l, &Bh[nt * 2]);
        }
    }

    // ---- register epilogue: out = acc + b2 + x (float2 stores) ----
    const int j  = lane & 3;
    const int rl = lane >> 2;
    #pragma unroll
    for (int mt = 0; mt < 2; mt++) {
        const int r0 = (w + mt * 8) * 16 + rl;      // rows r0, r0+8
        const float bi0 = __ldg(&b2[r0]);
        const float bi1 = __ldg(&b2[r0 + 8]);
        const float* xr0 = x + (size_t)(b * Cc + r0) * Ll + l0;
        const float* xr1 = xr0 + 8 * Ll;
        float* or0 = out + (size_t)(b * Cc + r0) * Ll + l0;
        float* or1 = or0 + 8 * Ll;
        #pragma unroll
        for (int nt = 0; nt < 4; nt++) {
            int co = nt * 8 + 2 * j;
            float2 x0 = *(const float2*)(xr0 + co);
            float2 x1 = *(const float2*)(xr1 + co);
            float2 o0, o1;
            o0.x = acc[mt][nt][0] + bi0 + x0.x;
            o0.y = acc[mt][nt][1] + bi0 + x0.y;
            o1.x = acc[mt][nt][2] + bi1 + x1.x;
            o1.y = acc[mt][nt][3] + bi1 + x1.y;
            *(float2*)(or0 + co) = o0;
            *(float2*)(or1 + co) = o1;
        }
    }
}

// ---------------------------------------------------------------------------
extern "C" void kernel_launch(void* const* d_in, const int* in_sizes, int n_in,
                              void* d_out, int out_size)
{
    const float* x     = (const float*)d_in[0];
    const float* gamma = (const float*)d_in[1];
    const float* beta  = (const float*)d_in[2];
    const float* w1    = (const float*)d_in[3];
    const float* b1    = (const float*)d_in[4];
    const float* wd    = (const float*)d_in[5];
    const float* bd    = (const float*)d_in[6];
    const float* wsm   = (const float*)d_in[7];
    const float* bs    = (const float*)d_in[8];
    const float* w2    = (const float*)d_in[9];
    const float* b2    = (const float*)d_in[10];
    float* out = (float*)d_out;

    k0_split<<<96, 256>>>(w1, w2);
    dim3 g1(NT1, Bb);
    k1_ln_pw1<<<g1, 256, K1_SMEM>>>(x, gamma, beta, b1, wd, bd);
    dim3 g3(Bb, 32);
    k3_scale<<<g3, 256>>>(wsm, bs);
    dim3 g4(Ll / 32, Bb);
    k4_pw2<<<g4, 256, K4_SMEM>>>(x, b2, out);
}

// round 11
// speedup vs baseline: 16.5275x; 1.1930x over previous
#include <cuda_runtime.h>
#include <cuda_fp16.h>
#include <math.h>
#include <stdint.h>

#define Bb 16
#define Cc 256
#define CC2 512
#define Ll 8192
#define EPSV 1e-5f
#define TLI1 30
#define NT1 274              // ceil(8192/30)

// scratch
__device__ float g_gate[Bb * Cc * Ll];
__device__ float g_pool[Bb * Cc];
__device__ float g_scale[Bb * Cc];
// weights pre-packed as mma.m16n8k16 A-fragments (fp16, single precision term):
//   index = (p * MT + mt) * 32 + lane, uint4 = {a0,a1,a2,a3}
__device__ uint4 g_w1f[16384];   // MT=32 (M=512), 16 panels
__device__ uint4 g_w2f[8192];    // MT=16 (M=256), 16 panels

// ---------------- helpers ----------------
__device__ __forceinline__ uint32_t smem_u32(const void* p) {
    uint32_t a;
    asm("{ .reg .u64 t; cvta.to.shared.u64 t, %1; cvt.u32.u64 %0, t; }" : "=r"(a) : "l"(p));
    return a;
}
__device__ __forceinline__ void ldsm4(uint32_t* r, uint32_t addr) {
    asm volatile("ldmatrix.sync.aligned.m8n8.x4.shared.b16 {%0,%1,%2,%3}, [%4];"
        : "=r"(r[0]), "=r"(r[1]), "=r"(r[2]), "=r"(r[3]) : "r"(addr));
}
__device__ __forceinline__ void mma16816(float* c, const uint32_t* a, const uint32_t* b) {
    asm volatile("mma.sync.aligned.m16n8k16.row.col.f32.f16.f16.f32 "
        "{%0,%1,%2,%3}, {%4,%5,%6,%7}, {%8,%9}, {%0,%1,%2,%3};"
        : "+f"(c[0]), "+f"(c[1]), "+f"(c[2]), "+f"(c[3])
        : "r"(a[0]), "r"(a[1]), "r"(a[2]), "r"(a[3]), "r"(b[0]), "r"(b[1]));
}
// fp16 pack: hi = rn(v), lo = rn(v - hi)
__device__ __forceinline__ uint32_t pack_hi2f(float v0, float v1, uint32_t* lo) {
    __half h0 = __float2half_rn(v0);
    __half h1 = __float2half_rn(v1);
    __half l0 = __float2half_rn(v0 - __half2float(h0));
    __half l1 = __float2half_rn(v1 - __half2float(h1));
    __half2 hp = __halves2half2(h0, h1);
    __half2 lp = __halves2half2(l0, l1);
    *lo = *reinterpret_cast<uint32_t*>(&lp);
    return *reinterpret_cast<uint32_t*>(&hp);
}
__device__ __forceinline__ uint32_t pack2f(float v0, float v1) {
    __half2 hp = __halves2half2(__float2half_rn(v0), __float2half_rn(v1));
    return *reinterpret_cast<uint32_t*>(&hp);
}
// B-tile byte offset: row l (n dim), channel c (k dim), swizzled for ldmatrix.
__device__ __forceinline__ uint32_t bswz(int l, int c) {
    return (uint32_t)(l * 512 + ((((c >> 3) ^ (l & 7)) << 4) | ((c & 7) * 2)));
}

// ---------------------------------------------------------------------------
// K0: pack weights into fp16 mma A-fragment layout; zero g_pool
// ---------------------------------------------------------------------------
__global__ __launch_bounds__(256) void k0_split(const float* __restrict__ w1,
                                                const float* __restrict__ w2)
{
    int idx = blockIdx.x * 256 + threadIdx.x;
    if (idx < Bb * Cc) g_pool[idx] = 0.f;

    if (idx < 16384) {                 // w1 fragments: MT=32
        int p = idx >> 10, rem = idx & 1023;
        int mt = rem >> 5, lane = rem & 31;
        int r = mt * 16 + (lane >> 2);
        int c = p * 16 + (lane & 3) * 2;
        const float* A = w1;
        uint4 hi;
        hi.x = pack2f(A[r * Cc + c],           A[r * Cc + c + 1]);
        hi.y = pack2f(A[(r + 8) * Cc + c],     A[(r + 8) * Cc + c + 1]);
        hi.z = pack2f(A[r * Cc + c + 8],       A[r * Cc + c + 9]);
        hi.w = pack2f(A[(r + 8) * Cc + c + 8], A[(r + 8) * Cc + c + 9]);
        g_w1f[idx] = hi;
    } else if (idx < 24576) {          // w2 fragments: MT=16
        int i2 = idx - 16384;
        int p = i2 >> 9, rem = i2 & 511;
        int mt = rem >> 5, lane = rem & 31;
        int r = mt * 16 + (lane >> 2);
        int c = p * 16 + (lane & 3) * 2;
        const float* A = w2;
        uint4 hi;
        hi.x = pack2f(A[r * Cc + c],           A[r * Cc + c + 1]);
        hi.y = pack2f(A[(r + 8) * Cc + c],     A[(r + 8) * Cc + c + 1]);
        hi.z = pack2f(A[r * Cc + c + 8],       A[r * Cc + c + 9]);
        hi.w = pack2f(A[(r + 8) * Cc + c + 8], A[(r + 8) * Cc + c + 9]);
        g_w2f[i2] = hi;
    }
}

// ---------------------------------------------------------------------------
// K1: LN + pw1 (M=512, N=32, fp16 2-term) + register dwconv + gate + pool
// 256 threads, 2 CTAs/SM. smem: B hi [0,16K) lo [16K,32K);
// red2 [32K,+2K) (aliased as redm later); stat [34K,+256)
// ---------------------------------------------------------------------------
#define K1_B    0
#define K1_RED  32768
#define K1_STAT 34816
#define K1_SMEM 35072

__global__ __launch_bounds__(256, 2) void k1_ln_pw1(
    const float* __restrict__ x, const float* __restrict__ gamma,
    const float* __restrict__ beta, const float* __restrict__ b1,
    const float* __restrict__ wd, const float* __restrict__ bd_)
{
    extern __shared__ char sm[];
    float* red2 = (float*)(sm + K1_RED);
    float* stat = (float*)(sm + K1_STAT);
    const uint32_t smb = smem_u32(sm);
    const int b    = blockIdx.y;
    const int tile = blockIdx.x;
    const int l0   = tile * TLI1 - 1;   // global l of local col 0
    const int tid  = threadIdx.x;
    const int w    = tid >> 5, lane = tid & 31;

    // ---- LN stats: warp w sums channels {w, w+8, ...} for column lane ----
    {
        int lg = l0 + lane;
        bool ok = (lg >= 0 && lg < Ll);
        float s = 0.f, sq = 0.f;
        if (ok) {
            const float* xp = x + (size_t)(b * Cc + w) * Ll + lg;
            for (int c = 0; c < 32; c++) {
                float v = __ldg(xp + (size_t)c * 8 * Ll);
                s += v; sq += v * v;
            }
        }
        red2[w * 32 + lane]       = s;
        red2[256 + w * 32 + lane] = sq;
    }
    __syncthreads();
    if (tid < 32) {
        float s = 0.f, sq = 0.f;
        #pragma unroll
        for (int k = 0; k < 8; k++) { s += red2[k * 32 + tid]; sq += red2[256 + k * 32 + tid]; }
        float mu = s * (1.f / Cc);
        float var = sq * (1.f / Cc) - mu * mu;
        stat[tid]      = mu;
        stat[32 + tid] = rsqrtf(var + EPSV);
    }
    __syncthreads();

    // ---- normalize (2nd x read, L2 hit) + fp16 split -> B tile [32 l][256 c]
    for (int i = tid; i < 128 * 32; i += 256) {
        int cp = i >> 5, l = i & 31;
        int c = cp * 2;
        int lg = l0 + l;
        bool ok = (lg >= 0 && lg < Ll);
        float x0 = ok ? __ldg(&x[(size_t)(b * Cc + c) * Ll + lg]) : 0.f;
        float x1 = ok ? __ldg(&x[(size_t)(b * Cc + c + 1) * Ll + lg]) : 0.f;
        float mu = stat[l], rs = stat[32 + l];
        float v0 = (x0 - mu) * rs * __ldg(&gamma[c]) + __ldg(&beta[c]);
        float v1 = (x1 - mu) * rs * __ldg(&gamma[c + 1]) + __ldg(&beta[c + 1]);
        uint32_t lop;
        uint32_t hip = pack_hi2f(v0, v1, &lop);
        uint32_t by = bswz(l, c);
        *(uint32_t*)(sm + K1_B + by)         = hip;
        *(uint32_t*)(sm + K1_B + 16384 + by) = lop;
    }
    __syncthreads();

    // ---- GEMM: M=512, N=32, K=256. warp w owns mt {w, w+8, w+16, w+24} ----
    const int lr  = lane & 7;
    const int gb0 = (lane >> 3) & 1;
    const int gb1 = lane >> 4;
    uint32_t bBase[2];
    #pragma unroll
    for (int bp = 0; bp < 2; bp++)
        bBase[bp] = smb + K1_B + (uint32_t)((bp * 16 + gb1 * 8 + lr) * 512);

    float acc[4][4][4];
    #pragma unroll
    for (int mi = 0; mi < 4; mi++)
        #pragma unroll
        for (int nt = 0; nt < 4; nt++)
            #pragma unroll
            for (int q = 0; q < 4; q++) acc[mi][nt][q] = 0.f;

    const uint4* AH[4];
    #pragma unroll
    for (int mi = 0; mi < 4; mi++) {
        int mt = w + mi * 8;
        AH[mi] = g_w1f + mt * 32 + lane;
    }

    #pragma unroll 4
    for (int p = 0; p < 16; ++p) {
        uint32_t kx = (uint32_t)(((p * 2 + gb0) ^ lr) << 4);
        uint32_t Bh[8], Bl[8];
        ldsm4(&Bh[0], bBase[0] + kx);
        ldsm4(&Bh[4], bBase[1] + kx);
        ldsm4(&Bl[0], bBase[0] + 16384 + kx);
        ldsm4(&Bl[4], bBase[1] + 16384 + kx);
        #pragma unroll
        for (int mi = 0; mi < 4; mi++) {
            uint4 ah = __ldg(AH[mi] + p * 1024);
            #pragma unroll
            for (int nt = 0; nt < 4; nt++) {
                mma16816(acc[mi][nt], (const uint32_t*)&ah, &Bh[nt * 2]);
                mma16816(acc[mi][nt], (const uint32_t*)&ah, &Bl[nt * 2]);
            }
        }
    }

    // ---- register epilogue: bias + dwconv (shfl halo) + gate + pool ----
    float* redm = red2;                 // alias (LN reductions long dead)
    const int j  = lane & 3;
    const int rl = lane >> 2;
    const int srcL = (lane & ~3) | ((j + 3) & 3);   // takes from lane j-1 (mod 4)
    const int srcR = (lane & ~3) | ((j + 1) & 3);   // takes from lane j+1 (mod 4)

    #pragma unroll
    for (int pair = 0; pair < 2; ++pair) {
        #pragma unroll
        for (int q = 0; q < 2; ++q) {
            const int m  = (w + pair * 8) * 16 + q * 8 + rl;
            const int m2 = m + Cc;
            const float biA = __ldg(&b1[m]);
            const float biB = __ldg(&b1[m2]);
            float zA0[4], zA1[4], zB0[4], zB1[4];
            #pragma unroll
            for (int nt = 0; nt < 4; nt++) {
                zA0[nt] = acc[pair][nt][q * 2]     + biA;
                zA1[nt] = acc[pair][nt][q * 2 + 1] + biA;
                zB0[nt] = acc[pair + 2][nt][q * 2]     + biB;
                zB1[nt] = acc[pair + 2][nt][q * 2 + 1] + biB;
            }
            float rA1[4], rA0[4], rB1[4], rB0[4];
            #pragma unroll
            for (int nt = 0; nt < 4; nt++) {
                rA1[nt] = __shfl_sync(0xFFFFFFFFu, zA1[nt], srcL);
                rA0[nt] = __shfl_sync(0xFFFFFFFFu, zA0[nt], srcR);
                rB1[nt] = __shfl_sync(0xFFFFFFFFu, zB1[nt], srcL);
                rB0[nt] = __shfl_sync(0xFFFFFFFFu, zB0[nt], srcR);
            }
            const float wa0 = __ldg(&wd[m * 3 + 0]),  wa1 = __ldg(&wd[m * 3 + 1]),
                        wa2 = __ldg(&wd[m * 3 + 2]),  ba  = __ldg(&bd_[m]);
            const float wb0 = __ldg(&wd[m2 * 3 + 0]), wb1 = __ldg(&wd[m2 * 3 + 1]),
                        wb2 = __ldg(&wd[m2 * 3 + 2]), bb  = __ldg(&bd_[m2]);
            float* orow = g_gate + (size_t)(b * Cc + m) * Ll;
            float psum = 0.f;
            #pragma unroll
            for (int nt = 0; nt < 4; nt++) {
                #pragma unroll
                for (int e = 0; e < 2; e++) {
                    int co = nt * 8 + 2 * j + e;
                    if (co >= 1 && co <= 30) {
                        int lg = l0 + co;
                        if (lg >= 0 && lg < Ll) {
                            float am1, ac, ap1, bm1, bc, bp1;
                            if (e == 0) {
                                am1 = (j == 0) ? (nt > 0 ? rA1[nt - 1] : 0.f) : rA1[nt];
                                bm1 = (j == 0) ? (nt > 0 ? rB1[nt - 1] : 0.f) : rB1[nt];
                                ac = zA0[nt]; ap1 = zA1[nt];
                                bc = zB0[nt]; bp1 = zB1[nt];
                            } else {
                                am1 = zA0[nt]; ac = zA1[nt];
                                bm1 = zB0[nt]; bc = zB1[nt];
                                ap1 = (j == 3) ? (nt < 3 ? rA0[nt + 1] : 0.f) : rA0[nt];
                                bp1 = (j == 3) ? (nt < 3 ? rB0[nt + 1] : 0.f) : rB0[nt];
                            }
                            if (lg - 1 < 0)   { am1 = 0.f; bm1 = 0.f; }
                            if (lg + 1 >= Ll) { ap1 = 0.f; bp1 = 0.f; }
                            float d1 = wa0 * am1 + wa1 * ac + wa2 * ap1 + ba;
                            float d2 = wb0 * bm1 + wb1 * bc + wb2 * bp1 + bb;
                            float g = d1 * d2;
                            orow[lg] = g;
                            psum += g;
                        }
                    }
                }
            }
            psum += __shfl_xor_sync(0xFFFFFFFFu, psum, 1);
            psum += __shfl_xor_sync(0xFFFFFFFFu, psum, 2);
            if (j == 0) redm[m] = psum;
        }
    }
    __syncthreads();
    if (tid < 256) {
        float v = redm[tid];
        if (v != 0.f) atomicAdd(&g_pool[b * Cc + tid], v * (1.f / Ll));
    }
}

// ---------------------------------------------------------------------------
// K3: SCA scale = sigmoid(ws @ pool + bs); one warp per output
// ---------------------------------------------------------------------------
__global__ __launch_bounds__(256) void k3_scale(
    const float* __restrict__ ws, const float* __restrict__ bs)
{
    __shared__ float sp[Cc];
    const int b = blockIdx.x;
    const int w = threadIdx.x >> 5, lane = threadIdx.x & 31;
    const int c = blockIdx.y * 8 + w;
    sp[threadIdx.x] = g_pool[b * Cc + threadIdx.x];
    __syncthreads();
    const float4* wr = (const float4*)(ws + c * Cc);
    const float4* pp = (const float4*)sp;
    float4 a0 = __ldg(&wr[lane * 2]), a1 = __ldg(&wr[lane * 2 + 1]);
    float4 p0 = pp[lane * 2], p1 = pp[lane * 2 + 1];
    float s = a0.x * p0.x + a0.y * p0.y + a0.z * p0.z + a0.w * p0.w
            + a1.x * p1.x + a1.y * p1.y + a1.z * p1.z + a1.w * p1.w;
    #pragma unroll
    for (int o = 16; o; o >>= 1) s += __shfl_xor_sync(0xFFFFFFFFu, s, o);
    if (lane == 0)
        g_scale[b * Cc + c] = 1.f / (1.f + expf(-(s + __ldg(&bs[c]))));
}

// ---------------------------------------------------------------------------
// K4: pw2 (M=256, N=32, fp16 2-term) + bias + residual, register epilogue.
// 256 threads, 3 CTAs/SM. smem: B hi [0,16K) lo [16K,32K)
// ---------------------------------------------------------------------------
#define K4_B 0
#define K4_SMEM 32768

__global__ __launch_bounds__(256, 3) void k4_pw2(
    const float* __restrict__ x, const float* __restrict__ b2,
    float* __restrict__ out)
{
    extern __shared__ char sm[];
    const uint32_t smb = smem_u32(sm);
    const int b = blockIdx.y, tile = blockIdx.x, tid = threadIdx.x;
    const int w = tid >> 5, lane = tid & 31;
    const int l0 = tile * 32;

    // ---- B tile: gate*scale -> fp16 split [32 l][256 c] ----
    for (int i = tid; i < 128 * 32; i += 256) {
        int cp = i >> 5, l = i & 31;
        int c = cp * 2;
        float v0 = g_gate[(size_t)(b * Cc + c) * Ll + l0 + l] * __ldg(&g_scale[b * Cc + c]);
        float v1 = g_gate[(size_t)(b * Cc + c + 1) * Ll + l0 + l] * __ldg(&g_scale[b * Cc + c + 1]);
        uint32_t lop;
        uint32_t hip = pack_hi2f(v0, v1, &lop);
        uint32_t by = bswz(l, c);
        *(uint32_t*)(sm + K4_B + by)         = hip;
        *(uint32_t*)(sm + K4_B + 16384 + by) = lop;
    }
    __syncthreads();

    const int lr  = lane & 7;
    const int gb0 = (lane >> 3) & 1;
    const int gb1 = lane >> 4;
    uint32_t bBase[2];
    #pragma unroll
    for (int bp = 0; bp < 2; bp++)
        bBase[bp] = smb + K4_B + (uint32_t)((bp * 16 + gb1 * 8 + lr) * 512);

    float acc[2][4][4];
    #pragma unroll
    for (int mt = 0; mt < 2; mt++)
        #pragma unroll
        for (int nt = 0; nt < 4; nt++)
            #pragma unroll
            for (int q = 0; q < 4; q++) acc[mt][nt][q] = 0.f;

    const uint4* A0H = g_w2f + w * 32 + lane;          // mt = w
    const uint4* A1H = g_w2f + (8 + w) * 32 + lane;    // mt = 8 + w

    #pragma unroll 4
    for (int p = 0; p < 16; ++p) {
        uint32_t kx = (uint32_t)(((p * 2 + gb0) ^ lr) << 4);
        uint32_t Bh[8], Bl[8];
        ldsm4(&Bh[0], bBase[0] + kx);
        ldsm4(&Bh[4], bBase[1] + kx);
        ldsm4(&Bl[0], bBase[0] + 16384 + kx);
        ldsm4(&Bl[4], bBase[1] + 16384 + kx);
        uint4 a0h = __ldg(A0H + p * 512);
        uint4 a1h = __ldg(A1H + p * 512);
        #pragma unroll
        for (int nt = 0; nt < 4; nt++) {
            mma16816(acc[0][nt], (const uint32_t*)&a0h, &Bh[nt * 2]);
            mma16816(acc[0][nt], (const uint32_t*)&a0h, &Bl[nt * 2]);
            mma16816(acc[1][nt], (const uint32_t*)&a1h, &Bh[nt * 2]);
            mma16816(acc[1][nt], (const uint32_t*)&a1h, &Bl[nt * 2]);
        }
    }

    // ---- register epilogue: out = acc + b2 + x (float2 stores) ----
    const int j  = lane & 3;
    const int rl = lane >> 2;
    #pragma unroll
    for (int mt = 0; mt < 2; mt++) {
        const int r0 = (w + mt * 8) * 16 + rl;      // rows r0, r0+8
        const float bi0 = __ldg(&b2[r0]);
        const float bi1 = __ldg(&b2[r0 + 8]);
        const float* xr0 = x + (size_t)(b * Cc + r0) * Ll + l0;
        const float* xr1 = xr0 + 8 * Ll;
        float* or0 = out + (size_t)(b * Cc + r0) * Ll + l0;
        float* or1 = or0 + 8 * Ll;
        #pragma unroll
        for (int nt = 0; nt < 4; nt++) {
            int co = nt * 8 + 2 * j;
            float2 x0 = *(const float2*)(xr0 + co);
            float2 x1 = *(const float2*)(xr1 + co);
            float2 o0, o1;
            o0.x = acc[mt][nt][0] + bi0 + x0.x;
            o0.y = acc[mt][nt][1] + bi0 + x0.y;
            o1.x = acc[mt][nt][2] + bi1 + x1.x;
            o1.y = acc[mt][nt][3] + bi1 + x1.y;
            *(float2*)(or0 + co) = o0;
            *(float2*)(or1 + co) = o1;
        }
    }
}

// ---------------------------------------------------------------------------
extern "C" void kernel_launch(void* const* d_in, const int* in_sizes, int n_in,
                              void* d_out, int out_size)
{
    const float* x     = (const float*)d_in[0];
    const float* gamma = (const float*)d_in[1];
    const float* beta  = (const float*)d_in[2];
    const float* w1    = (const float*)d_in[3];
    const float* b1    = (const float*)d_in[4];
    const float* wd    = (const float*)d_in[5];
    const float* bd    = (const float*)d_in[6];
    const float* wsm   = (const float*)d_in[7];
    const float* bs    = (const float*)d_in[8];
    const float* w2    = (const float*)d_in[9];
    const float* b2    = (const float*)d_in[10];
    float* out = (float*)d_out;

    k0_split<<<96, 256>>>(w1, w2);
    dim3 g1(NT1, Bb);
    k1_ln_pw1<<<g1, 256, K1_SMEM>>>(x, gamma, beta, b1, wd, bd);
    dim3 g3(Bb, 32);
    k3_scale<<<g3, 256>>>(wsm, bs);
    dim3 g4(Ll / 32, Bb);
    k4_pw2<<<g4, 256, K4_SMEM>>>(x, b2, out);
}